// round 1
// baseline (speedup 1.0000x reference)
#include <cuda_runtime.h>
#include <cuda_bf16.h>
#include <cstddef>

#define B_    2
#define T_    1024
#define MTOK  2048      // B*T
#define H_    2048
#define V_    32000
#define HK_   16
#define HV_   32
#define DK_   128
#define DV_   128
#define QKDIM 2048
#define VDIM  4096
#define CDIM  8192      // 2*QKDIM + VDIM
#define QKVZ_N 12288    // 2*QKDIM + 2*VDIM

// -------------------- scratch (device globals; no allocs allowed) --------------------
__device__ float g_x[MTOK * H_];          // embeddings          [M,2048]
__device__ float g_qkvz[(size_t)MTOK * QKVZ_N]; // qkvz pre-conv  [M,12288]
__device__ float g_ba[MTOK * 64];         // b,a                  [M,64]
__device__ float g_conv[(size_t)MTOK * CDIM];   // post conv+silu [M,8192]
__device__ float g_qn[MTOK * QKDIM];      // normalized q (HK heads)
__device__ float g_kn[MTOK * QKDIM];      // normalized k (HK heads)
__device__ float g_g[MTOK * HV_];         // log-decay
__device__ float g_beta[MTOK * HV_];      // beta
__device__ float g_o[(size_t)MTOK * VDIM];// scan output / gated-norm in place
__device__ float g_h[MTOK * H_];          // after W_out

// -------------------- embed gather --------------------
__global__ void embed_kernel(const int* __restrict__ ids, const float* __restrict__ tab,
                             float* __restrict__ x) {
    int m = blockIdx.x;
    int id = ids[m];
    const float4* src = reinterpret_cast<const float4*>(tab + (size_t)id * H_);
    float4* dst = reinterpret_cast<float4*>(x + (size_t)m * H_);
    for (int i = threadIdx.x; i < H_ / 4; i += blockDim.x) dst[i] = src[i];
}

// -------------------- fp32 SGEMM: C[M,N] = A[M,K] @ B[K,N], row-major --------------------
// 128x128 block, BK=8, 256 threads, 8x8 microtile. Requires M%128==0, K%8==0, N%4==0.
__global__ __launch_bounds__(256) void sgemm128(int M, int N, int K,
                                                const float* __restrict__ A,
                                                const float* __restrict__ Bm,
                                                float* __restrict__ C) {
    __shared__ float As[8][128];
    __shared__ float Bs[8][128];
    int tid = threadIdx.x;
    int cRow = blockIdx.y << 7;
    int cCol = blockIdx.x << 7;

    int aRow = tid >> 1;            // 0..127
    int aCol = (tid & 1) << 2;      // 0 or 4
    int bRow = tid >> 5;            // 0..7
    int bCol = (tid & 31) << 2;     // 0..124

    int tr = (tid >> 4) << 3;       // 0..120
    int tc = (tid & 15) << 3;       // 0..120

    float acc[8][8];
#pragma unroll
    for (int i = 0; i < 8; i++)
#pragma unroll
        for (int j = 0; j < 8; j++) acc[i][j] = 0.f;

    const float* aptr = A + (size_t)(cRow + aRow) * K + aCol;
    bool bok = (cCol + bCol) < N;
    const float* bptr = Bm + (size_t)bRow * N + cCol + bCol;

    for (int k0 = 0; k0 < K; k0 += 8) {
        float4 av = *reinterpret_cast<const float4*>(aptr + k0);
        As[aCol + 0][aRow] = av.x;
        As[aCol + 1][aRow] = av.y;
        As[aCol + 2][aRow] = av.z;
        As[aCol + 3][aRow] = av.w;
        float4 bv = make_float4(0.f, 0.f, 0.f, 0.f);
        if (bok) bv = *reinterpret_cast<const float4*>(bptr + (size_t)k0 * N);
        *reinterpret_cast<float4*>(&Bs[bRow][bCol]) = bv;
        __syncthreads();
#pragma unroll
        for (int kk = 0; kk < 8; kk++) {
            float4 a0 = *reinterpret_cast<const float4*>(&As[kk][tr]);
            float4 a1 = *reinterpret_cast<const float4*>(&As[kk][tr + 4]);
            float4 b0 = *reinterpret_cast<const float4*>(&Bs[kk][tc]);
            float4 b1 = *reinterpret_cast<const float4*>(&Bs[kk][tc + 4]);
            float ar[8] = {a0.x, a0.y, a0.z, a0.w, a1.x, a1.y, a1.z, a1.w};
            float br[8] = {b0.x, b0.y, b0.z, b0.w, b1.x, b1.y, b1.z, b1.w};
#pragma unroll
            for (int i = 0; i < 8; i++)
#pragma unroll
                for (int j = 0; j < 8; j++) acc[i][j] += ar[i] * br[j];
        }
        __syncthreads();
    }
#pragma unroll
    for (int i = 0; i < 8; i++) {
        size_t r = (size_t)(cRow + tr + i);
#pragma unroll
        for (int j = 0; j < 8; j += 4) {
            int c = cCol + tc + j;
            if (c < N) {
                float4 v = make_float4(acc[i][j], acc[i][j + 1], acc[i][j + 2], acc[i][j + 3]);
                *reinterpret_cast<float4*>(C + r * N + c) = v;
            }
        }
    }
}

// -------------------- causal depthwise conv (K=4) + SiLU over channels [0,8192) --------------------
__global__ void conv_silu_kernel(const float* __restrict__ qkvz, const float* __restrict__ cw,
                                 const float* __restrict__ cb, float* __restrict__ out) {
    int idx = blockIdx.x * blockDim.x + threadIdx.x;  // over MTOK*CDIM
    int c = idx & (CDIM - 1);
    int m = idx >> 13;
    int t = m & (T_ - 1);
    const float* w = cw + c * 4;
    float s = cb[c];
#pragma unroll
    for (int j = 0; j < 4; j++) {
        int tt = t - 3 + j;
        if (tt >= 0) s += w[j] * qkvz[(size_t)(m - 3 + j) * QKVZ_N + c];
    }
    out[(size_t)m * CDIM + c] = s / (1.f + expf(-s));
}

// -------------------- l2norm of q (scaled) and k per (m, HK head) --------------------
__global__ __launch_bounds__(128) void norm_qk_kernel(const float* __restrict__ conv,
                                                      float* __restrict__ qn,
                                                      float* __restrict__ kn) {
    int m = blockIdx.x >> 4;
    int hh = blockIdx.x & 15;
    int i = threadIdx.x;
    const float* qr = conv + (size_t)m * CDIM + hh * DK_;
    const float* kr = conv + (size_t)m * CDIM + QKDIM + hh * DK_;
    float qv = qr[i], kv = kr[i];
    float q2 = qv * qv, k2 = kv * kv;
#pragma unroll
    for (int off = 16; off; off >>= 1) {
        q2 += __shfl_xor_sync(0xffffffffu, q2, off);
        k2 += __shfl_xor_sync(0xffffffffu, k2, off);
    }
    __shared__ float shq[4], shk[4];
    if ((i & 31) == 0) { shq[i >> 5] = q2; shk[i >> 5] = k2; }
    __syncthreads();
    float sq = shq[0] + shq[1] + shq[2] + shq[3];
    float sk = shk[0] + shk[1] + shk[2] + shk[3];
    qn[(size_t)m * QKDIM + hh * DK_ + i] = qv * rsqrtf(sq + 1e-6f) * 0.08838834764831845f; // DK^-0.5
    kn[(size_t)m * QKDIM + hh * DK_ + i] = kv * rsqrtf(sk + 1e-6f);
}

// -------------------- beta = sigmoid(b);  g = -exp(A_log)*softplus(a+dt_bias) --------------------
__global__ void gates_kernel(const float* __restrict__ ba, const float* __restrict__ A_log,
                             const float* __restrict__ dtb, float* __restrict__ g,
                             float* __restrict__ beta) {
    int m = blockIdx.x;
    int h = threadIdx.x;  // 32
    float bv = ba[m * 64 + h];
    float av = ba[m * 64 + 32 + h];
    beta[m * HV_ + h] = 1.f / (1.f + expf(-bv));
    float x = av + dtb[h];
    float sp = (x > 20.f) ? x : log1pf(expf(x));
    g[m * HV_ + h] = -expf(A_log[h]) * sp;
}

// -------------------- sequential gated delta-rule scan --------------------
// DV columns of S are independent -> split DV into 2 segments of 64.
// grid = B*HV*2 = 128 blocks (one wave), 256 threads: thread = (vloc 0..63, kseg 0..3),
// each thread owns S[kseg*32 .. +32, v] in registers.
__global__ __launch_bounds__(256) void scan_kernel(const float* __restrict__ qn,
                                                   const float* __restrict__ kn,
                                                   const float* __restrict__ conv,
                                                   const float* __restrict__ gg,
                                                   const float* __restrict__ bb,
                                                   float* __restrict__ o) {
    int bid = blockIdx.x;           // 0..127
    int split = bid & 1;
    int h = (bid >> 1) & 31;
    int b = bid >> 6;
    int kh = h >> 1;                // GQA: HV head -> HK head
    int v0 = split * 64;
    int tid = threadIdx.x;
    int vloc = tid >> 2;
    int kseg = tid & 3;
    int k0 = kseg * 32;

    __shared__ float sk[2][128], sq[2][128];

    float S[32];
#pragma unroll
    for (int i = 0; i < 32; i++) S[i] = 0.f;

    const float* qrow = qn + (size_t)(b * T_) * QKDIM + kh * DK_;
    const float* krow = kn + (size_t)(b * T_) * QKDIM + kh * DK_;
    const float* vrow = conv + (size_t)(b * T_) * CDIM + 2 * QKDIM + h * DV_ + v0 + vloc;
    const float* grow = gg + (b * T_) * HV_ + h;
    const float* brow = bb + (b * T_) * HV_ + h;
    float* orow = o + (size_t)(b * T_) * VDIM + h * DV_ + v0 + vloc;

    for (int t = 0; t < T_; t++) {
        int p = t & 1;
        if (tid < 128) sk[p][tid] = krow[(size_t)t * QKDIM + tid];
        else           sq[p][tid - 128] = qrow[(size_t)t * QKDIM + (tid - 128)];
        float gt = grow[(size_t)t * HV_];
        float bt = brow[(size_t)t * HV_];
        float vt = vrow[(size_t)t * CDIM];
        __syncthreads();
        float decay = expf(gt);
        float pkv = 0.f;
#pragma unroll
        for (int i = 0; i < 32; i++) {
            float s = S[i] * decay;
            S[i] = s;
            pkv += sk[p][k0 + i] * s;
        }
        pkv += __shfl_xor_sync(0xffffffffu, pkv, 1);
        pkv += __shfl_xor_sync(0xffffffffu, pkv, 2);
        float delta = (vt - pkv) * bt;
        float po = 0.f;
#pragma unroll
        for (int i = 0; i < 32; i++) {
            float s = S[i] + sk[p][k0 + i] * delta;
            S[i] = s;
            po += sq[p][k0 + i] * s;
        }
        po += __shfl_xor_sync(0xffffffffu, po, 1);
        po += __shfl_xor_sync(0xffffffffu, po, 2);
        if (kseg == 0) orow[(size_t)t * VDIM] = po;
    }
}

// -------------------- gated RMSNorm (in place on o): o = rmsnorm(o*silu(z))*norm_w --------------------
__global__ __launch_bounds__(128) void gated_norm_kernel(float* __restrict__ o,
                                                         const float* __restrict__ qkvz,
                                                         const float* __restrict__ nw) {
    int m = blockIdx.x >> 5;
    int h = blockIdx.x & 31;
    int i = threadIdx.x;
    size_t oidx = (size_t)m * VDIM + h * DV_ + i;
    float ov = o[oidx];
    float zv = qkvz[(size_t)m * QKVZ_N + 2 * QKDIM + VDIM + h * DV_ + i];
    float gv = ov * (zv / (1.f + expf(-zv)));
    float s2 = gv * gv;
#pragma unroll
    for (int off = 16; off; off >>= 1) s2 += __shfl_xor_sync(0xffffffffu, s2, off);
    __shared__ float sh[4];
    if ((i & 31) == 0) sh[i >> 5] = s2;
    __syncthreads();
    float mean = (sh[0] + sh[1] + sh[2] + sh[3]) * (1.f / 128.f);
    o[oidx] = gv * rsqrtf(mean + 1e-6f) * nw[i];
}

// -------------------- launch --------------------
extern "C" void kernel_launch(void* const* d_in, const int* in_sizes, int n_in,
                              void* d_out, int out_size) {
    const int*   ids   = (const int*)d_in[0];
    const float* tab   = (const float*)d_in[1];
    const float* Wqkvz = (const float*)d_in[2];
    const float* Wba   = (const float*)d_in[3];
    const float* cw    = (const float*)d_in[4];
    const float* cb    = (const float*)d_in[5];
    const float* A_log = (const float*)d_in[6];
    const float* dtb   = (const float*)d_in[7];
    const float* nw    = (const float*)d_in[8];
    const float* Wout  = (const float*)d_in[9];
    const float* Wlm   = (const float*)d_in[10];
    float* out = (float*)d_out;

    float *x, *qkvz, *ba, *conv, *qn, *kn, *gg, *bb, *o, *hbuf;
    cudaGetSymbolAddress((void**)&x,    g_x);
    cudaGetSymbolAddress((void**)&qkvz, g_qkvz);
    cudaGetSymbolAddress((void**)&ba,   g_ba);
    cudaGetSymbolAddress((void**)&conv, g_conv);
    cudaGetSymbolAddress((void**)&qn,   g_qn);
    cudaGetSymbolAddress((void**)&kn,   g_kn);
    cudaGetSymbolAddress((void**)&gg,   g_g);
    cudaGetSymbolAddress((void**)&bb,   g_beta);
    cudaGetSymbolAddress((void**)&o,    g_o);
    cudaGetSymbolAddress((void**)&hbuf, g_h);

    embed_kernel<<<MTOK, 256>>>(ids, tab, x);
    sgemm128<<<dim3(QKVZ_N / 128, MTOK / 128), 256>>>(MTOK, QKVZ_N, H_, x, Wqkvz, qkvz);
    sgemm128<<<dim3(1, MTOK / 128), 256>>>(MTOK, 64, H_, x, Wba, ba);
    conv_silu_kernel<<<(MTOK * CDIM) / 256, 256>>>(qkvz, cw, cb, conv);
    norm_qk_kernel<<<MTOK * HK_, 128>>>(conv, qn, kn);
    gates_kernel<<<MTOK, 32>>>(ba, A_log, dtb, gg, bb);
    scan_kernel<<<B_ * HV_ * 2, 256>>>(qn, kn, conv, gg, bb, o);
    gated_norm_kernel<<<MTOK * HV_, 128>>>(o, qkvz, nw);
    sgemm128<<<dim3(H_ / 128, MTOK / 128), 256>>>(MTOK, H_, VDIM, o, Wout, hbuf);
    sgemm128<<<dim3(V_ / 128, MTOK / 128), 256>>>(MTOK, V_, H_, hbuf, Wlm, out);
}

// round 2
// speedup vs baseline: 2.2671x; 2.2671x over previous
#include <cuda_runtime.h>
#include <cuda_bf16.h>
#include <cstddef>

#define B_    2
#define T_    1024
#define MTOK  2048      // B*T
#define H_    2048
#define V_    32000
#define HK_   16
#define HV_   32
#define DK_   128
#define DV_   128
#define QKDIM 2048
#define VDIM  4096
#define CDIM  8192      // 2*QKDIM + VDIM
#define QKVZ_N 12288    // 2*QKDIM + 2*VDIM

typedef __nv_bfloat16 bf16;

// -------------------- scratch (device globals; no allocs allowed) --------------------
__device__ float g_x[MTOK * H_];                 // embeddings [M,2048]
__device__ float g_qkvz[(size_t)MTOK * QKVZ_N];  // qkvz pre-conv [M,12288]
__device__ float g_ba[MTOK * 64];
__device__ float g_conv[(size_t)MTOK * CDIM];
__device__ float g_qn[MTOK * QKDIM];
__device__ float g_kn[MTOK * QKDIM];
__device__ float g_g[MTOK * HV_];
__device__ float g_beta[MTOK * HV_];
__device__ float g_o[(size_t)MTOK * VDIM];
__device__ float g_h[MTOK * H_];

// bf16 split buffers (hi/lo)
__device__ bf16 g_xh[MTOK * H_],        g_xl[MTOK * H_];
__device__ bf16 g_Wqkvzh[(size_t)H_ * QKVZ_N], g_Wqkvzl[(size_t)H_ * QKVZ_N];
__device__ bf16 g_Wouth[(size_t)VDIM * H_],    g_Woutl[(size_t)VDIM * H_];
__device__ bf16 g_Wlmh[(size_t)H_ * V_],       g_Wlml[(size_t)H_ * V_];
__device__ bf16 g_oh[(size_t)MTOK * VDIM],     g_ol[(size_t)MTOK * VDIM];
__device__ bf16 g_hh[MTOK * H_],       g_hl[MTOK * H_];

// -------------------- embed gather --------------------
__global__ void embed_kernel(const int* __restrict__ ids, const float* __restrict__ tab,
                             float* __restrict__ x) {
    int m = blockIdx.x;
    int id = ids[m];
    const float4* src = reinterpret_cast<const float4*>(tab + (size_t)id * H_);
    float4* dst = reinterpret_cast<float4*>(x + (size_t)m * H_);
    for (int i = threadIdx.x; i < H_ / 4; i += blockDim.x) dst[i] = src[i];
}

// -------------------- fp32 -> bf16 hi/lo split (vectorized, 4 per thread) --------------------
__global__ void split_kernel(const float* __restrict__ src, bf16* __restrict__ hi,
                             bf16* __restrict__ lo, size_t n4) {
    size_t i = (size_t)blockIdx.x * blockDim.x + threadIdx.x;
    if (i >= n4) return;
    float4 v = reinterpret_cast<const float4*>(src)[i];
    bf16 h0 = __float2bfloat16(v.x), h1 = __float2bfloat16(v.y);
    bf16 h2 = __float2bfloat16(v.z), h3 = __float2bfloat16(v.w);
    bf16 l0 = __float2bfloat16(v.x - __bfloat162float(h0));
    bf16 l1 = __float2bfloat16(v.y - __bfloat162float(h1));
    bf16 l2 = __float2bfloat16(v.z - __bfloat162float(h2));
    bf16 l3 = __float2bfloat16(v.w - __bfloat162float(h3));
    __nv_bfloat162* ph = reinterpret_cast<__nv_bfloat162*>(hi);
    __nv_bfloat162* pl = reinterpret_cast<__nv_bfloat162*>(lo);
    ph[2 * i + 0] = __nv_bfloat162(h0, h1);
    ph[2 * i + 1] = __nv_bfloat162(h2, h3);
    pl[2 * i + 0] = __nv_bfloat162(l0, l1);
    pl[2 * i + 1] = __nv_bfloat162(l2, l3);
}

// -------------------- bf16x3 tensor-core GEMM: C[M,N] = A @ B (both split hi/lo) --------------------
// Block 128x128, k-step 16, 256 threads = 8 warps (2m x 4n), warp tile 64x32.
// Requires M%128==0, N%128==0, K%16==0.
#define ASTRIDE 18   // bf16 elements per row in smem (16 + 2 pad)
__device__ __forceinline__ unsigned lds32(const bf16* p) {
    return *reinterpret_cast<const unsigned*>(p);
}
__device__ __forceinline__ void mma16816(float* c, const unsigned* a, const unsigned* b) {
    asm volatile(
        "mma.sync.aligned.m16n8k16.row.col.f32.bf16.bf16.f32 "
        "{%0,%1,%2,%3}, {%4,%5,%6,%7}, {%8,%9}, {%0,%1,%2,%3};\n"
        : "+f"(c[0]), "+f"(c[1]), "+f"(c[2]), "+f"(c[3])
        : "r"(a[0]), "r"(a[1]), "r"(a[2]), "r"(a[3]), "r"(b[0]), "r"(b[1]));
}

__global__ __launch_bounds__(256, 1) void gemm_bf16x3(
    int M, int N, int K,
    const bf16* __restrict__ Ah, const bf16* __restrict__ Al,
    const bf16* __restrict__ Bh, const bf16* __restrict__ Bl,
    float* __restrict__ C) {
    __shared__ bf16 sA[2][2][128 * ASTRIDE];  // [stage][hi/lo][m*ASTRIDE+k]
    __shared__ bf16 sB[2][2][128 * ASTRIDE];  // [stage][hi/lo][n*ASTRIDE+k]

    int tid = threadIdx.x;
    int lane = tid & 31, wid = tid >> 5;
    int wm = wid >> 2, wn = wid & 3;
    int g = lane >> 2, tig = lane & 3;

    int row0 = blockIdx.y << 7;
    int col0 = blockIdx.x << 7;

    // A-tile loader: row aRow (0..127), 8 cols starting aHalf*8
    int aRow = tid >> 1, aHalf = (tid & 1) << 3;
    // B-tile loader: row bRow (0..15), 8 cols starting bCol
    int bRow = tid >> 4, bCol = (tid & 15) << 3;

    const uint4* pAh = reinterpret_cast<const uint4*>(Ah + (size_t)(row0 + aRow) * K + aHalf);
    const uint4* pAl = reinterpret_cast<const uint4*>(Al + (size_t)(row0 + aRow) * K + aHalf);
    const bf16*  pBh = Bh + (size_t)bRow * N + col0 + bCol;
    const bf16*  pBl = Bl + (size_t)bRow * N + col0 + bCol;

    float acc[4][4][4];
#pragma unroll
    for (int i = 0; i < 4; i++)
#pragma unroll
        for (int j = 0; j < 4; j++)
#pragma unroll
            for (int r = 0; r < 4; r++) acc[i][j][r] = 0.f;

    int nk = K >> 4;

    // helpers to store tiles
    auto storeA = [&](int st, uint4 vh, uint4 vl) {
        unsigned* dh = reinterpret_cast<unsigned*>(&sA[st][0][aRow * ASTRIDE + aHalf]);
        unsigned* dl = reinterpret_cast<unsigned*>(&sA[st][1][aRow * ASTRIDE + aHalf]);
        dh[0] = vh.x; dh[1] = vh.y; dh[2] = vh.z; dh[3] = vh.w;
        dl[0] = vl.x; dl[1] = vl.y; dl[2] = vl.z; dl[3] = vl.w;
    };
    auto storeB = [&](int st, uint4 vh, uint4 vl) {
        union { uint4 v; bf16 e[8]; } uh, ul;
        uh.v = vh; ul.v = vl;
#pragma unroll
        for (int j = 0; j < 8; j++) {
            sB[st][0][(bCol + j) * ASTRIDE + bRow] = uh.e[j];
            sB[st][1][(bCol + j) * ASTRIDE + bRow] = ul.e[j];
        }
    };

    // prologue: chunk 0 -> stage 0
    {
        uint4 vah = pAh[0], val = pAl[0];
        uint4 vbh = *reinterpret_cast<const uint4*>(pBh);
        uint4 vbl = *reinterpret_cast<const uint4*>(pBl);
        storeA(0, vah, val);
        storeB(0, vbh, vbl);
    }
    __syncthreads();

    for (int kc = 0; kc < nk; kc++) {
        int st = kc & 1;
        uint4 vah, val, vbh, vbl;
        bool more = (kc + 1) < nk;
        if (more) {
            int k0 = (kc + 1) << 4;
            vah = pAh[k0 >> 3];  // uint4 = 8 bf16
            val = pAl[k0 >> 3];
            vbh = *reinterpret_cast<const uint4*>(pBh + (size_t)k0 * N);
            vbl = *reinterpret_cast<const uint4*>(pBl + (size_t)k0 * N);
        }

        // fragment loads
        const bf16* Ahs = sA[st][0];
        const bf16* Als = sA[st][1];
        const bf16* Bhs = sB[st][0];
        const bf16* Bls = sB[st][1];
        unsigned fah[4][4], fal[4][4], fbh[4][2], fbl[4][2];
#pragma unroll
        for (int mi = 0; mi < 4; mi++) {
            int r = (wm << 6) + (mi << 4) + g;
            fah[mi][0] = lds32(Ahs + r * ASTRIDE + 2 * tig);
            fah[mi][1] = lds32(Ahs + (r + 8) * ASTRIDE + 2 * tig);
            fah[mi][2] = lds32(Ahs + r * ASTRIDE + 2 * tig + 8);
            fah[mi][3] = lds32(Ahs + (r + 8) * ASTRIDE + 2 * tig + 8);
            fal[mi][0] = lds32(Als + r * ASTRIDE + 2 * tig);
            fal[mi][1] = lds32(Als + (r + 8) * ASTRIDE + 2 * tig);
            fal[mi][2] = lds32(Als + r * ASTRIDE + 2 * tig + 8);
            fal[mi][3] = lds32(Als + (r + 8) * ASTRIDE + 2 * tig + 8);
        }
#pragma unroll
        for (int ni = 0; ni < 4; ni++) {
            int c = (wn << 5) + (ni << 3) + g;
            fbh[ni][0] = lds32(Bhs + c * ASTRIDE + 2 * tig);
            fbh[ni][1] = lds32(Bhs + c * ASTRIDE + 2 * tig + 8);
            fbl[ni][0] = lds32(Bls + c * ASTRIDE + 2 * tig);
            fbl[ni][1] = lds32(Bls + c * ASTRIDE + 2 * tig + 8);
        }
#pragma unroll
        for (int mi = 0; mi < 4; mi++)
#pragma unroll
            for (int ni = 0; ni < 4; ni++) {
                mma16816(acc[mi][ni], fah[mi], fbh[ni]);
                mma16816(acc[mi][ni], fah[mi], fbl[ni]);
                mma16816(acc[mi][ni], fal[mi], fbh[ni]);
            }

        if (more) storeA(st ^ 1, vah, val), storeB(st ^ 1, vbh, vbl);
        __syncthreads();
    }

    // epilogue
#pragma unroll
    for (int mi = 0; mi < 4; mi++) {
        int r = row0 + (wm << 6) + (mi << 4) + g;
#pragma unroll
        for (int ni = 0; ni < 4; ni++) {
            int c = col0 + (wn << 5) + (ni << 3) + 2 * tig;
            *reinterpret_cast<float2*>(C + (size_t)r * N + c) =
                make_float2(acc[mi][ni][0], acc[mi][ni][1]);
            *reinterpret_cast<float2*>(C + (size_t)(r + 8) * N + c) =
                make_float2(acc[mi][ni][2], acc[mi][ni][3]);
        }
    }
}

// -------------------- fp32 SGEMM (small N; used for ba) --------------------
__global__ __launch_bounds__(256) void sgemm128(int M, int N, int K,
                                                const float* __restrict__ A,
                                                const float* __restrict__ Bm,
                                                float* __restrict__ C) {
    __shared__ float As[8][128];
    __shared__ float Bs[8][128];
    int tid = threadIdx.x;
    int cRow = blockIdx.y << 7;
    int cCol = blockIdx.x << 7;
    int aRow = tid >> 1, aCol = (tid & 1) << 2;
    int bRow = tid >> 5, bCol = (tid & 31) << 2;
    int tr = (tid >> 4) << 3, tc = (tid & 15) << 3;
    float acc[8][8];
#pragma unroll
    for (int i = 0; i < 8; i++)
#pragma unroll
        for (int j = 0; j < 8; j++) acc[i][j] = 0.f;
    const float* aptr = A + (size_t)(cRow + aRow) * K + aCol;
    bool bok = (cCol + bCol) < N;
    const float* bptr = Bm + (size_t)bRow * N + cCol + bCol;
    for (int k0 = 0; k0 < K; k0 += 8) {
        float4 av = *reinterpret_cast<const float4*>(aptr + k0);
        As[aCol + 0][aRow] = av.x; As[aCol + 1][aRow] = av.y;
        As[aCol + 2][aRow] = av.z; As[aCol + 3][aRow] = av.w;
        float4 bv = make_float4(0.f, 0.f, 0.f, 0.f);
        if (bok) bv = *reinterpret_cast<const float4*>(bptr + (size_t)k0 * N);
        *reinterpret_cast<float4*>(&Bs[bRow][bCol]) = bv;
        __syncthreads();
#pragma unroll
        for (int kk = 0; kk < 8; kk++) {
            float4 a0 = *reinterpret_cast<const float4*>(&As[kk][tr]);
            float4 a1 = *reinterpret_cast<const float4*>(&As[kk][tr + 4]);
            float4 b0 = *reinterpret_cast<const float4*>(&Bs[kk][tc]);
            float4 b1 = *reinterpret_cast<const float4*>(&Bs[kk][tc + 4]);
            float ar[8] = {a0.x, a0.y, a0.z, a0.w, a1.x, a1.y, a1.z, a1.w};
            float br[8] = {b0.x, b0.y, b0.z, b0.w, b1.x, b1.y, b1.z, b1.w};
#pragma unroll
            for (int i = 0; i < 8; i++)
#pragma unroll
                for (int j = 0; j < 8; j++) acc[i][j] += ar[i] * br[j];
        }
        __syncthreads();
    }
#pragma unroll
    for (int i = 0; i < 8; i++) {
        size_t r = (size_t)(cRow + tr + i);
#pragma unroll
        for (int j = 0; j < 8; j += 4) {
            int c = cCol + tc + j;
            if (c < N)
                *reinterpret_cast<float4*>(C + r * N + c) =
                    make_float4(acc[i][j], acc[i][j + 1], acc[i][j + 2], acc[i][j + 3]);
        }
    }
}

// -------------------- causal depthwise conv (K=4) + SiLU --------------------
__global__ void conv_silu_kernel(const float* __restrict__ qkvz, const float* __restrict__ cw,
                                 const float* __restrict__ cb, float* __restrict__ out) {
    int idx = blockIdx.x * blockDim.x + threadIdx.x;
    int c = idx & (CDIM - 1);
    int m = idx >> 13;
    int t = m & (T_ - 1);
    const float* w = cw + c * 4;
    float s = cb[c];
#pragma unroll
    for (int j = 0; j < 4; j++) {
        int tt = t - 3 + j;
        if (tt >= 0) s += w[j] * qkvz[(size_t)(m - 3 + j) * QKVZ_N + c];
    }
    out[(size_t)m * CDIM + c] = s / (1.f + expf(-s));
}

// -------------------- l2norm q/k --------------------
__global__ __launch_bounds__(128) void norm_qk_kernel(const float* __restrict__ conv,
                                                      float* __restrict__ qn,
                                                      float* __restrict__ kn) {
    int m = blockIdx.x >> 4;
    int hh = blockIdx.x & 15;
    int i = threadIdx.x;
    const float* qr = conv + (size_t)m * CDIM + hh * DK_;
    const float* kr = conv + (size_t)m * CDIM + QKDIM + hh * DK_;
    float qv = qr[i], kv = kr[i];
    float q2 = qv * qv, k2 = kv * kv;
#pragma unroll
    for (int off = 16; off; off >>= 1) {
        q2 += __shfl_xor_sync(0xffffffffu, q2, off);
        k2 += __shfl_xor_sync(0xffffffffu, k2, off);
    }
    __shared__ float shq[4], shk[4];
    if ((i & 31) == 0) { shq[i >> 5] = q2; shk[i >> 5] = k2; }
    __syncthreads();
    float sq = shq[0] + shq[1] + shq[2] + shq[3];
    float sk = shk[0] + shk[1] + shk[2] + shk[3];
    qn[(size_t)m * QKDIM + hh * DK_ + i] = qv * rsqrtf(sq + 1e-6f) * 0.08838834764831845f;
    kn[(size_t)m * QKDIM + hh * DK_ + i] = kv * rsqrtf(sk + 1e-6f);
}

// -------------------- gates --------------------
__global__ void gates_kernel(const float* __restrict__ ba, const float* __restrict__ A_log,
                             const float* __restrict__ dtb, float* __restrict__ g,
                             float* __restrict__ beta) {
    int m = blockIdx.x;
    int h = threadIdx.x;
    float bv = ba[m * 64 + h];
    float av = ba[m * 64 + 32 + h];
    beta[m * HV_ + h] = 1.f / (1.f + expf(-bv));
    float x = av + dtb[h];
    float sp = (x > 20.f) ? x : log1pf(expf(x));
    g[m * HV_ + h] = -expf(A_log[h]) * sp;
}

// -------------------- sequential gated delta-rule scan --------------------
__global__ __launch_bounds__(256) void scan_kernel(const float* __restrict__ qn,
                                                   const float* __restrict__ kn,
                                                   const float* __restrict__ conv,
                                                   const float* __restrict__ gg,
                                                   const float* __restrict__ bb,
                                                   float* __restrict__ o) {
    int bid = blockIdx.x;
    int split = bid & 1;
    int h = (bid >> 1) & 31;
    int b = bid >> 6;
    int kh = h >> 1;
    int v0 = split * 64;
    int tid = threadIdx.x;
    int vloc = tid >> 2;
    int kseg = tid & 3;
    int k0 = kseg * 32;

    __shared__ float sk[2][128], sq[2][128];

    float S[32];
#pragma unroll
    for (int i = 0; i < 32; i++) S[i] = 0.f;

    const float* qrow = qn + (size_t)(b * T_) * QKDIM + kh * DK_;
    const float* krow = kn + (size_t)(b * T_) * QKDIM + kh * DK_;
    const float* vrow = conv + (size_t)(b * T_) * CDIM + 2 * QKDIM + h * DV_ + v0 + vloc;
    const float* grow = gg + (b * T_) * HV_ + h;
    const float* brow = bb + (b * T_) * HV_ + h;
    float* orow = o + (size_t)(b * T_) * VDIM + h * DV_ + v0 + vloc;

    for (int t = 0; t < T_; t++) {
        int p = t & 1;
        if (tid < 128) sk[p][tid] = krow[(size_t)t * QKDIM + tid];
        else           sq[p][tid - 128] = qrow[(size_t)t * QKDIM + (tid - 128)];
        float gt = grow[(size_t)t * HV_];
        float bt = brow[(size_t)t * HV_];
        float vt = vrow[(size_t)t * CDIM];
        __syncthreads();
        float decay = expf(gt);
        float pkv = 0.f;
#pragma unroll
        for (int i = 0; i < 32; i++) {
            float s = S[i] * decay;
            S[i] = s;
            pkv += sk[p][k0 + i] * s;
        }
        pkv += __shfl_xor_sync(0xffffffffu, pkv, 1);
        pkv += __shfl_xor_sync(0xffffffffu, pkv, 2);
        float delta = (vt - pkv) * bt;
        float po = 0.f;
#pragma unroll
        for (int i = 0; i < 32; i++) {
            float s = S[i] + sk[p][k0 + i] * delta;
            S[i] = s;
            po += sq[p][k0 + i] * s;
        }
        po += __shfl_xor_sync(0xffffffffu, po, 1);
        po += __shfl_xor_sync(0xffffffffu, po, 2);
        if (kseg == 0) orow[(size_t)t * VDIM] = po;
    }
}

// -------------------- gated RMSNorm --------------------
__global__ __launch_bounds__(128) void gated_norm_kernel(float* __restrict__ o,
                                                         const float* __restrict__ qkvz,
                                                         const float* __restrict__ nw) {
    int m = blockIdx.x >> 5;
    int h = blockIdx.x & 31;
    int i = threadIdx.x;
    size_t oidx = (size_t)m * VDIM + h * DV_ + i;
    float ov = o[oidx];
    float zv = qkvz[(size_t)m * QKVZ_N + 2 * QKDIM + VDIM + h * DV_ + i];
    float gv = ov * (zv / (1.f + expf(-zv)));
    float s2 = gv * gv;
#pragma unroll
    for (int off = 16; off; off >>= 1) s2 += __shfl_xor_sync(0xffffffffu, s2, off);
    __shared__ float sh[4];
    if ((i & 31) == 0) sh[i >> 5] = s2;
    __syncthreads();
    float mean = (sh[0] + sh[1] + sh[2] + sh[3]) * (1.f / 128.f);
    o[oidx] = gv * rsqrtf(mean + 1e-6f) * nw[i];
}

// -------------------- launch --------------------
static inline void do_split(const float* src, bf16* hi, bf16* lo, size_t n) {
    size_t n4 = n / 4;
    int blocks = (int)((n4 + 255) / 256);
    split_kernel<<<blocks, 256>>>(src, hi, lo, n4);
}

extern "C" void kernel_launch(void* const* d_in, const int* in_sizes, int n_in,
                              void* d_out, int out_size) {
    const int*   ids   = (const int*)d_in[0];
    const float* tab   = (const float*)d_in[1];
    const float* Wqkvz = (const float*)d_in[2];
    const float* Wba   = (const float*)d_in[3];
    const float* cw    = (const float*)d_in[4];
    const float* cb    = (const float*)d_in[5];
    const float* A_log = (const float*)d_in[6];
    const float* dtb   = (const float*)d_in[7];
    const float* nw    = (const float*)d_in[8];
    const float* Wout  = (const float*)d_in[9];
    const float* Wlm   = (const float*)d_in[10];
    float* out = (float*)d_out;

    float *x, *qkvz, *ba, *conv, *qn, *kn, *gg, *bb, *o, *hbuf;
    cudaGetSymbolAddress((void**)&x,    g_x);
    cudaGetSymbolAddress((void**)&qkvz, g_qkvz);
    cudaGetSymbolAddress((void**)&ba,   g_ba);
    cudaGetSymbolAddress((void**)&conv, g_conv);
    cudaGetSymbolAddress((void**)&qn,   g_qn);
    cudaGetSymbolAddress((void**)&kn,   g_kn);
    cudaGetSymbolAddress((void**)&gg,   g_g);
    cudaGetSymbolAddress((void**)&bb,   g_beta);
    cudaGetSymbolAddress((void**)&o,    g_o);
    cudaGetSymbolAddress((void**)&hbuf, g_h);

    bf16 *xh, *xl, *Wqh, *Wql, *Woh, *Wol, *Wlh, *Wll, *oh, *ol, *hh, *hl;
    cudaGetSymbolAddress((void**)&xh,  g_xh);   cudaGetSymbolAddress((void**)&xl,  g_xl);
    cudaGetSymbolAddress((void**)&Wqh, g_Wqkvzh); cudaGetSymbolAddress((void**)&Wql, g_Wqkvzl);
    cudaGetSymbolAddress((void**)&Woh, g_Wouth); cudaGetSymbolAddress((void**)&Wol, g_Woutl);
    cudaGetSymbolAddress((void**)&Wlh, g_Wlmh);  cudaGetSymbolAddress((void**)&Wll, g_Wlml);
    cudaGetSymbolAddress((void**)&oh,  g_oh);    cudaGetSymbolAddress((void**)&ol,  g_ol);
    cudaGetSymbolAddress((void**)&hh,  g_hh);    cudaGetSymbolAddress((void**)&hl,  g_hl);

    // weight splits (independent of activations)
    do_split(Wqkvz, Wqh, Wql, (size_t)H_ * QKVZ_N);
    do_split(Wout,  Woh, Wol, (size_t)VDIM * H_);
    do_split(Wlm,   Wlh, Wll, (size_t)H_ * V_);

    embed_kernel<<<MTOK, 256>>>(ids, tab, x);
    do_split(x, xh, xl, (size_t)MTOK * H_);
    gemm_bf16x3<<<dim3(QKVZ_N / 128, MTOK / 128), 256>>>(MTOK, QKVZ_N, H_, xh, xl, Wqh, Wql, qkvz);
    sgemm128<<<dim3(1, MTOK / 128), 256>>>(MTOK, 64, H_, x, Wba, ba);
    conv_silu_kernel<<<(MTOK * CDIM) / 256, 256>>>(qkvz, cw, cb, conv);
    norm_qk_kernel<<<MTOK * HK_, 128>>>(conv, qn, kn);
    gates_kernel<<<MTOK, 32>>>(ba, A_log, dtb, gg, bb);
    scan_kernel<<<B_ * HV_ * 2, 256>>>(qn, kn, conv, gg, bb, o);
    gated_norm_kernel<<<MTOK * HV_, 128>>>(o, qkvz, nw);
    do_split(o, oh, ol, (size_t)MTOK * VDIM);
    gemm_bf16x3<<<dim3(H_ / 128, MTOK / 128), 256>>>(MTOK, H_, VDIM, oh, ol, Woh, Wol, hbuf);
    do_split(hbuf, hh, hl, (size_t)MTOK * H_);
    gemm_bf16x3<<<dim3(V_ / 128, MTOK / 128), 256>>>(MTOK, V_, H_, hh, hl, Wlh, Wll, out);
}

// round 7
// speedup vs baseline: 3.4588x; 1.5257x over previous
#include <cuda_runtime.h>
#include <cuda_bf16.h>
#include <cstdint>
#include <cstddef>

#define B_    2
#define T_    1024
#define MTOK  2048
#define H_    2048
#define V_    32000
#define HK_   16
#define HV_   32
#define DK_   128
#define DV_   128
#define QKDIM 2048
#define VDIM  4096
#define CDIM  8192
#define QKVZ_N 12288

typedef __nv_bfloat16 bf16;

// ==================== scratch ====================
__device__ float g_x[MTOK * H_];
__device__ float g_qkvz[(size_t)MTOK * QKVZ_N];
__device__ float g_ba[MTOK * 64];
__device__ float g_conv[(size_t)MTOK * CDIM];
__device__ float g_qn[MTOK * QKDIM];
__device__ float g_kn[MTOK * QKDIM];
__device__ float g_g[MTOK * HV_];
__device__ float g_beta[MTOK * HV_];
__device__ float g_o[(size_t)MTOK * VDIM];

// split activations [M,K] and transposed split weights [N,K]
__device__ bf16 g_xh[MTOK * H_],  g_xl[MTOK * H_];
__device__ bf16 g_oh[(size_t)MTOK * VDIM], g_ol[(size_t)MTOK * VDIM];
__device__ bf16 g_hh[MTOK * H_],  g_hl[MTOK * H_];
__device__ bf16 g_Wqh[(size_t)QKVZ_N * H_], g_Wql[(size_t)QKVZ_N * H_];
__device__ bf16 g_Woh[(size_t)H_ * VDIM],   g_Wol[(size_t)H_ * VDIM];
__device__ bf16 g_Wlh[(size_t)V_ * H_],     g_Wll[(size_t)V_ * H_];

// ==================== helpers ====================
__device__ __forceinline__ uint32_t smem_u32(const void* p) {
    uint32_t a;
    asm("{ .reg .u64 t; cvta.to.shared.u64 t, %1; cvt.u32.u64 %0, t; }" : "=r"(a) : "l"(p));
    return a;
}
__device__ __forceinline__ void cpa16(uint32_t dst, const void* src) {
    asm volatile("cp.async.cg.shared.global [%0], [%1], 16;" :: "r"(dst), "l"(src) : "memory");
}
#define CPA_COMMIT() asm volatile("cp.async.commit_group;" ::: "memory")
#define CPA_WAIT2()  asm volatile("cp.async.wait_group 2;" ::: "memory")

__device__ __forceinline__ void ldm_x4(uint32_t* r, uint32_t addr) {
    asm volatile("ldmatrix.sync.aligned.m8n8.x4.shared.b16 {%0,%1,%2,%3}, [%4];"
                 : "=r"(r[0]), "=r"(r[1]), "=r"(r[2]), "=r"(r[3]) : "r"(addr));
}
__device__ __forceinline__ void mma16816(float* c, const uint32_t* a, const uint32_t* b) {
    asm volatile(
        "mma.sync.aligned.m16n8k16.row.col.f32.bf16.bf16.f32 "
        "{%0,%1,%2,%3}, {%4,%5,%6,%7}, {%8,%9}, {%0,%1,%2,%3};\n"
        : "+f"(c[0]), "+f"(c[1]), "+f"(c[2]), "+f"(c[3])
        : "r"(a[0]), "r"(a[1]), "r"(a[2]), "r"(a[3]), "r"(b[0]), "r"(b[1]));
}
#define SWZ(off) ((off) ^ (((off) >> 3) & 0x70))

// ==================== bf16x3 mma.sync GEMM ====================
// C[M,N] = A[M,K] @ Bt^T, Bt is [N,K]; both hi/lo split. Block 128x128, BK=64,
// 3-stage cp.async pipeline, ldmatrix on SW128-swizzled smem, 256 threads (8 warps 2x4).
#define STG_BYTES 65536
#define O_AL 16384
#define O_BH 32768
#define O_BL 49152
#define GEMM_SMEM (3 * STG_BYTES + 1024)

__global__ __launch_bounds__(256, 1) void gemm_mma(
    int M, int N, int K,
    const bf16* __restrict__ Ah, const bf16* __restrict__ Al,
    const bf16* __restrict__ Bh, const bf16* __restrict__ Bl,
    float* __restrict__ Cf, bf16* __restrict__ Chi, bf16* __restrict__ Clo) {
    extern __shared__ char dsm_raw[];
    uint32_t dbase = (smem_u32(dsm_raw) + 1023u) & ~1023u;

    int tid = threadIdx.x;
    int lane = tid & 31, wid = tid >> 5;
    int wm = wid >> 2, wn = wid & 3;                 // warp tile 64(m) x 32(n)
    int row0 = blockIdx.x << 7;                      // m fastest: n-stripe L2 reuse
    int col0 = blockIdx.y << 7;

    // ldmatrix per-lane addressing pieces
    int lrow = ((lane >> 3) & 1) * 8 + (lane & 7);   // row within 16-row tile group
    int lbyte = (lane >> 4) * 16;                    // 0 or 16 (k half)
    int rowA = wm * 64 + lrow;
    int rowB = wn * 32 + lrow;

    // loader indices: each thread covers 4 chunks of 16B per array per stage
    int ldRow = tid >> 1;                            // 0..127 (x2 over i)
    // chunk id c = tid + i*256 : row = c>>3, c8 = c&7
    (void)ldRow;

    float acc[4][4][4];
#pragma unroll
    for (int i = 0; i < 4; i++)
#pragma unroll
        for (int j = 0; j < 4; j++)
#pragma unroll
            for (int r = 0; r < 4; r++) acc[i][j][r] = 0.f;

    int nk = K >> 6;

    auto load_stage = [&](int slot, int kc) {
        uint32_t stg = dbase + slot * STG_BYTES;
        int k0 = kc << 6;
#pragma unroll
        for (int i = 0; i < 4; i++) {
            int c = tid + (i << 8);
            int row = c >> 3, c8 = c & 7;
            uint32_t sw = SWZ((uint32_t)(row * 128 + c8 * 16));
            size_t ga = (size_t)(row0 + row) * K + k0 + c8 * 8;
            size_t gb = (size_t)(col0 + row) * K + k0 + c8 * 8;
            cpa16(stg + sw, Ah + ga);
            cpa16(stg + O_AL + sw, Al + ga);
            cpa16(stg + O_BH + sw, Bh + gb);
            cpa16(stg + O_BL + sw, Bl + gb);
        }
    };

    // prologue: 3 stages in flight
    load_stage(0, 0); CPA_COMMIT();
    load_stage(1, 1); CPA_COMMIT();
    load_stage(2, 2); CPA_COMMIT();

    for (int kc = 0; kc < nk; kc++) {
        CPA_WAIT2();
        __syncthreads();
        uint32_t stg = dbase + (kc % 3) * STG_BYTES;
#pragma unroll
        for (int kk = 0; kk < 4; kk++) {
            uint32_t fah[4][4], fal[4][4], fbh[4][2], fbl[4][2];
#pragma unroll
            for (int mi = 0; mi < 4; mi++) {
                uint32_t off = SWZ((uint32_t)((rowA + mi * 16) * 128 + kk * 32 + lbyte));
                ldm_x4(fah[mi], stg + off);
                ldm_x4(fal[mi], stg + O_AL + off);
            }
#pragma unroll
            for (int nj = 0; nj < 2; nj++) {
                uint32_t off = SWZ((uint32_t)((rowB + nj * 16) * 128 + kk * 32 + lbyte));
                uint32_t rh[4], rl[4];
                ldm_x4(rh, stg + O_BH + off);
                ldm_x4(rl, stg + O_BL + off);
                fbh[nj * 2][0] = rh[0]; fbh[nj * 2][1] = rh[2];
                fbh[nj * 2 + 1][0] = rh[1]; fbh[nj * 2 + 1][1] = rh[3];
                fbl[nj * 2][0] = rl[0]; fbl[nj * 2][1] = rl[2];
                fbl[nj * 2 + 1][0] = rl[1]; fbl[nj * 2 + 1][1] = rl[3];
            }
#pragma unroll
            for (int mi = 0; mi < 4; mi++)
#pragma unroll
                for (int ni = 0; ni < 4; ni++) {
                    mma16816(acc[mi][ni], fah[mi], fbh[ni]);
                    mma16816(acc[mi][ni], fah[mi], fbl[ni]);
                    mma16816(acc[mi][ni], fal[mi], fbh[ni]);
                }
        }
        __syncthreads();
        if (kc + 3 < nk) load_stage(kc % 3, kc + 3);
        CPA_COMMIT();
    }

    // epilogue
    int g = lane >> 2, tig = lane & 3;
#pragma unroll
    for (int mi = 0; mi < 4; mi++) {
        int r = row0 + wm * 64 + mi * 16 + g;
#pragma unroll
        for (int ni = 0; ni < 4; ni++) {
            int c = col0 + wn * 32 + ni * 8 + 2 * tig;
            float a0 = acc[mi][ni][0], a1 = acc[mi][ni][1];
            float a2 = acc[mi][ni][2], a3 = acc[mi][ni][3];
            if (Cf) {
                *reinterpret_cast<float2*>(Cf + (size_t)r * N + c) = make_float2(a0, a1);
                *reinterpret_cast<float2*>(Cf + (size_t)(r + 8) * N + c) = make_float2(a2, a3);
            }
            if (Chi) {
                bf16 h0 = __float2bfloat16(a0), h1 = __float2bfloat16(a1);
                bf16 h2 = __float2bfloat16(a2), h3 = __float2bfloat16(a3);
                bf16 l0 = __float2bfloat16(a0 - __bfloat162float(h0));
                bf16 l1 = __float2bfloat16(a1 - __bfloat162float(h1));
                bf16 l2 = __float2bfloat16(a2 - __bfloat162float(h2));
                bf16 l3 = __float2bfloat16(a3 - __bfloat162float(h3));
                *reinterpret_cast<__nv_bfloat162*>(Chi + (size_t)r * N + c) = __nv_bfloat162(h0, h1);
                *reinterpret_cast<__nv_bfloat162*>(Chi + (size_t)(r + 8) * N + c) = __nv_bfloat162(h2, h3);
                *reinterpret_cast<__nv_bfloat162*>(Clo + (size_t)r * N + c) = __nv_bfloat162(l0, l1);
                *reinterpret_cast<__nv_bfloat162*>(Clo + (size_t)(r + 8) * N + c) = __nv_bfloat162(l2, l3);
            }
        }
    }
}

// ==================== embed + split ====================
__global__ void embed_split_kernel(const int* __restrict__ ids, const float* __restrict__ tab,
                                   float* __restrict__ x, bf16* __restrict__ xh,
                                   bf16* __restrict__ xl) {
    int m = blockIdx.x;
    int id = ids[m];
    const float4* src = reinterpret_cast<const float4*>(tab + (size_t)id * H_);
    float4* dst = reinterpret_cast<float4*>(x + (size_t)m * H_);
    __nv_bfloat162* ph = reinterpret_cast<__nv_bfloat162*>(xh) + (size_t)m * (H_ / 2);
    __nv_bfloat162* pl = reinterpret_cast<__nv_bfloat162*>(xl) + (size_t)m * (H_ / 2);
    for (int i = threadIdx.x; i < H_ / 4; i += blockDim.x) {
        float4 v = src[i];
        dst[i] = v;
        bf16 h0 = __float2bfloat16(v.x), h1 = __float2bfloat16(v.y);
        bf16 h2 = __float2bfloat16(v.z), h3 = __float2bfloat16(v.w);
        bf16 l0 = __float2bfloat16(v.x - __bfloat162float(h0));
        bf16 l1 = __float2bfloat16(v.y - __bfloat162float(h1));
        bf16 l2 = __float2bfloat16(v.z - __bfloat162float(h2));
        bf16 l3 = __float2bfloat16(v.w - __bfloat162float(h3));
        ph[2 * i + 0] = __nv_bfloat162(h0, h1);
        ph[2 * i + 1] = __nv_bfloat162(h2, h3);
        pl[2 * i + 0] = __nv_bfloat162(l0, l1);
        pl[2 * i + 1] = __nv_bfloat162(l2, l3);
    }
}

// ==================== transpose + split weights: W[K,N] -> [N,K] hi/lo ====================
__global__ __launch_bounds__(256) void tsplit_kernel(const float* __restrict__ W,
                                                     bf16* __restrict__ Th, bf16* __restrict__ Tl,
                                                     int K, int N) {
    __shared__ float tile[32][33];
    int kb = blockIdx.x << 5, nb = blockIdx.y << 5;
    int tx = threadIdx.x, ty = threadIdx.y;  // (32, 8)
#pragma unroll
    for (int j = 0; j < 4; j++)
        tile[ty + j * 8][tx] = W[(size_t)(kb + ty + j * 8) * N + nb + tx];
    __syncthreads();
#pragma unroll
    for (int j = 0; j < 4; j++) {
        float v = tile[tx][ty + j * 8];
        bf16 h = __float2bfloat16(v);
        bf16 l = __float2bfloat16(v - __bfloat162float(h));
        size_t oidx = (size_t)(nb + ty + j * 8) * K + kb + tx;
        Th[oidx] = h;
        Tl[oidx] = l;
    }
}

// ==================== small fp32 SGEMM (ba: N=64) ====================
__global__ __launch_bounds__(256) void sgemm128(int M, int N, int K,
                                                const float* __restrict__ A,
                                                const float* __restrict__ Bm,
                                                float* __restrict__ C) {
    __shared__ float As[8][128];
    __shared__ float Bs[8][128];
    int tid = threadIdx.x;
    int cRow = blockIdx.y << 7;
    int cCol = blockIdx.x << 7;
    int aRow = tid >> 1, aCol = (tid & 1) << 2;
    int bRow = tid >> 5, bCol = (tid & 31) << 2;
    int tr = (tid >> 4) << 3, tc = (tid & 15) << 3;
    float acc[8][8];
#pragma unroll
    for (int i = 0; i < 8; i++)
#pragma unroll
        for (int j = 0; j < 8; j++) acc[i][j] = 0.f;
    const float* aptr = A + (size_t)(cRow + aRow) * K + aCol;
    bool bok = (cCol + bCol) < N;
    const float* bptr = Bm + (size_t)bRow * N + cCol + bCol;
    for (int k0 = 0; k0 < K; k0 += 8) {
        float4 av = *reinterpret_cast<const float4*>(aptr + k0);
        As[aCol + 0][aRow] = av.x; As[aCol + 1][aRow] = av.y;
        As[aCol + 2][aRow] = av.z; As[aCol + 3][aRow] = av.w;
        float4 bv = make_float4(0.f, 0.f, 0.f, 0.f);
        if (bok) bv = *reinterpret_cast<const float4*>(bptr + (size_t)k0 * N);
        *reinterpret_cast<float4*>(&Bs[bRow][bCol]) = bv;
        __syncthreads();
#pragma unroll
        for (int kk = 0; kk < 8; kk++) {
            float4 a0 = *reinterpret_cast<const float4*>(&As[kk][tr]);
            float4 a1 = *reinterpret_cast<const float4*>(&As[kk][tr + 4]);
            float4 b0 = *reinterpret_cast<const float4*>(&Bs[kk][tc]);
            float4 b1 = *reinterpret_cast<const float4*>(&Bs[kk][tc + 4]);
            float ar[8] = {a0.x, a0.y, a0.z, a0.w, a1.x, a1.y, a1.z, a1.w};
            float br[8] = {b0.x, b0.y, b0.z, b0.w, b1.x, b1.y, b1.z, b1.w};
#pragma unroll
            for (int i = 0; i < 8; i++)
#pragma unroll
                for (int j = 0; j < 8; j++) acc[i][j] += ar[i] * br[j];
        }
        __syncthreads();
    }
#pragma unroll
    for (int i = 0; i < 8; i++) {
        size_t r = (size_t)(cRow + tr + i);
#pragma unroll
        for (int j = 0; j < 8; j += 4) {
            int c = cCol + tc + j;
            if (c < N)
                *reinterpret_cast<float4*>(C + r * N + c) =
                    make_float4(acc[i][j], acc[i][j + 1], acc[i][j + 2], acc[i][j + 3]);
        }
    }
}

// ==================== conv + silu ====================
__global__ void conv_silu_kernel(const float* __restrict__ qkvz, const float* __restrict__ cw,
                                 const float* __restrict__ cb, float* __restrict__ out) {
    int idx = blockIdx.x * blockDim.x + threadIdx.x;
    int c = idx & (CDIM - 1);
    int m = idx >> 13;
    int t = m & (T_ - 1);
    const float* w = cw + c * 4;
    float s = cb[c];
#pragma unroll
    for (int j = 0; j < 4; j++) {
        int tt = t - 3 + j;
        if (tt >= 0) s += w[j] * qkvz[(size_t)(m - 3 + j) * QKVZ_N + c];
    }
    out[(size_t)m * CDIM + c] = s / (1.f + expf(-s));
}

// ==================== l2norm q/k ====================
__global__ __launch_bounds__(128) void norm_qk_kernel(const float* __restrict__ conv,
                                                      float* __restrict__ qn,
                                                      float* __restrict__ kn) {
    int m = blockIdx.x >> 4;
    int hh = blockIdx.x & 15;
    int i = threadIdx.x;
    const float* qr = conv + (size_t)m * CDIM + hh * DK_;
    const float* kr = conv + (size_t)m * CDIM + QKDIM + hh * DK_;
    float qv = qr[i], kv = kr[i];
    float q2 = qv * qv, k2 = kv * kv;
#pragma unroll
    for (int off = 16; off; off >>= 1) {
        q2 += __shfl_xor_sync(0xffffffffu, q2, off);
        k2 += __shfl_xor_sync(0xffffffffu, k2, off);
    }
    __shared__ float shq[4], shk[4];
    if ((i & 31) == 0) { shq[i >> 5] = q2; shk[i >> 5] = k2; }
    __syncthreads();
    float sq = shq[0] + shq[1] + shq[2] + shq[3];
    float sk = shk[0] + shk[1] + shk[2] + shk[3];
    qn[(size_t)m * QKDIM + hh * DK_ + i] = qv * rsqrtf(sq + 1e-6f) * 0.08838834764831845f;
    kn[(size_t)m * QKDIM + hh * DK_ + i] = kv * rsqrtf(sk + 1e-6f);
}

// ==================== gates ====================
__global__ void gates_kernel(const float* __restrict__ ba, const float* __restrict__ A_log,
                             const float* __restrict__ dtb, float* __restrict__ g,
                             float* __restrict__ beta) {
    int m = blockIdx.x;
    int h = threadIdx.x;
    float bv = ba[m * 64 + h];
    float av = ba[m * 64 + 32 + h];
    beta[m * HV_ + h] = 1.f / (1.f + expf(-bv));
    float x = av + dtb[h];
    float sp = (x > 20.f) ? x : log1pf(expf(x));
    g[m * HV_ + h] = -expf(A_log[h]) * sp;
}

// ==================== scan ====================
__global__ __launch_bounds__(256) void scan_kernel(const float* __restrict__ qn,
                                                   const float* __restrict__ kn,
                                                   const float* __restrict__ conv,
                                                   const float* __restrict__ gg,
                                                   const float* __restrict__ bb,
                                                   float* __restrict__ o) {
    int bid = blockIdx.x;
    int split = bid & 1;
    int h = (bid >> 1) & 31;
    int b = bid >> 6;
    int kh = h >> 1;
    int v0 = split * 64;
    int tid = threadIdx.x;
    int vloc = tid >> 2;
    int kseg = tid & 3;
    int k0 = kseg * 32;

    __shared__ float sk[2][128], sq[2][128];

    float S[32];
#pragma unroll
    for (int i = 0; i < 32; i++) S[i] = 0.f;

    const float* qrow = qn + (size_t)(b * T_) * QKDIM + kh * DK_;
    const float* krow = kn + (size_t)(b * T_) * QKDIM + kh * DK_;
    const float* vrow = conv + (size_t)(b * T_) * CDIM + 2 * QKDIM + h * DV_ + v0 + vloc;
    const float* grow = gg + (b * T_) * HV_ + h;
    const float* brow = bb + (b * T_) * HV_ + h;
    float* orow = o + (size_t)(b * T_) * VDIM + h * DV_ + v0 + vloc;

    for (int t = 0; t < T_; t++) {
        int p = t & 1;
        if (tid < 128) sk[p][tid] = krow[(size_t)t * QKDIM + tid];
        else           sq[p][tid - 128] = qrow[(size_t)t * QKDIM + (tid - 128)];
        float gt = grow[(size_t)t * HV_];
        float bt = brow[(size_t)t * HV_];
        float vt = vrow[(size_t)t * CDIM];
        __syncthreads();
        float decay = expf(gt);
        float pkv = 0.f;
#pragma unroll
        for (int i = 0; i < 32; i++) {
            float s = S[i] * decay;
            S[i] = s;
            pkv += sk[p][k0 + i] * s;
        }
        pkv += __shfl_xor_sync(0xffffffffu, pkv, 1);
        pkv += __shfl_xor_sync(0xffffffffu, pkv, 2);
        float delta = (vt - pkv) * bt;
        float po = 0.f;
#pragma unroll
        for (int i = 0; i < 32; i++) {
            float s = S[i] + sk[p][k0 + i] * delta;
            S[i] = s;
            po += sq[p][k0 + i] * s;
        }
        po += __shfl_xor_sync(0xffffffffu, po, 1);
        po += __shfl_xor_sync(0xffffffffu, po, 2);
        if (kseg == 0) orow[(size_t)t * VDIM] = po;
    }
}

// ==================== gated RMSNorm + split ====================
__global__ __launch_bounds__(128) void gated_norm_split(const float* __restrict__ o,
                                                        const float* __restrict__ qkvz,
                                                        const float* __restrict__ nw,
                                                        bf16* __restrict__ oh,
                                                        bf16* __restrict__ ol) {
    int m = blockIdx.x >> 5;
    int h = blockIdx.x & 31;
    int i = threadIdx.x;
    size_t oidx = (size_t)m * VDIM + h * DV_ + i;
    float ov = o[oidx];
    float zv = qkvz[(size_t)m * QKVZ_N + 2 * QKDIM + VDIM + h * DV_ + i];
    float gv = ov * (zv / (1.f + expf(-zv)));
    float s2 = gv * gv;
#pragma unroll
    for (int off = 16; off; off >>= 1) s2 += __shfl_xor_sync(0xffffffffu, s2, off);
    __shared__ float sh[4];
    if ((i & 31) == 0) sh[i >> 5] = s2;
    __syncthreads();
    float mean = (sh[0] + sh[1] + sh[2] + sh[3]) * (1.f / 128.f);
    float val = gv * rsqrtf(mean + 1e-6f) * nw[i];
    bf16 hh = __float2bfloat16(val);
    bf16 ll = __float2bfloat16(val - __bfloat162float(hh));
    oh[oidx] = hh;
    ol[oidx] = ll;
}

// ==================== launch ====================
extern "C" void kernel_launch(void* const* d_in, const int* in_sizes, int n_in,
                              void* d_out, int out_size) {
    const int*   ids   = (const int*)d_in[0];
    const float* tab   = (const float*)d_in[1];
    const float* Wqkvz = (const float*)d_in[2];
    const float* Wba   = (const float*)d_in[3];
    const float* cw    = (const float*)d_in[4];
    const float* cb    = (const float*)d_in[5];
    const float* A_log = (const float*)d_in[6];
    const float* dtb   = (const float*)d_in[7];
    const float* nw    = (const float*)d_in[8];
    const float* Wout  = (const float*)d_in[9];
    const float* Wlm   = (const float*)d_in[10];
    float* out = (float*)d_out;

    cudaFuncSetAttribute(gemm_mma, cudaFuncAttributeMaxDynamicSharedMemorySize, GEMM_SMEM);

    float *x, *qkvz, *ba, *conv, *qn, *kn, *gg, *bb, *o;
    cudaGetSymbolAddress((void**)&x,    g_x);
    cudaGetSymbolAddress((void**)&qkvz, g_qkvz);
    cudaGetSymbolAddress((void**)&ba,   g_ba);
    cudaGetSymbolAddress((void**)&conv, g_conv);
    cudaGetSymbolAddress((void**)&qn,   g_qn);
    cudaGetSymbolAddress((void**)&kn,   g_kn);
    cudaGetSymbolAddress((void**)&gg,   g_g);
    cudaGetSymbolAddress((void**)&bb,   g_beta);
    cudaGetSymbolAddress((void**)&o,    g_o);

    bf16 *xh, *xl, *oh, *ol, *hh, *hl, *Wqh, *Wql, *Woh, *Wol, *Wlh, *Wll;
    cudaGetSymbolAddress((void**)&xh, g_xh);  cudaGetSymbolAddress((void**)&xl, g_xl);
    cudaGetSymbolAddress((void**)&oh, g_oh);  cudaGetSymbolAddress((void**)&ol, g_ol);
    cudaGetSymbolAddress((void**)&hh, g_hh);  cudaGetSymbolAddress((void**)&hl, g_hl);
    cudaGetSymbolAddress((void**)&Wqh, g_Wqh); cudaGetSymbolAddress((void**)&Wql, g_Wql);
    cudaGetSymbolAddress((void**)&Woh, g_Woh); cudaGetSymbolAddress((void**)&Wol, g_Wol);
    cudaGetSymbolAddress((void**)&Wlh, g_Wlh); cudaGetSymbolAddress((void**)&Wll, g_Wll);

    // weight transpose + split: W[K,N] -> [N,K]
    tsplit_kernel<<<dim3(H_ / 32, QKVZ_N / 32), dim3(32, 8)>>>(Wqkvz, Wqh, Wql, H_, QKVZ_N);
    tsplit_kernel<<<dim3(VDIM / 32, H_ / 32),   dim3(32, 8)>>>(Wout,  Woh, Wol, VDIM, H_);
    tsplit_kernel<<<dim3(H_ / 32, V_ / 32),     dim3(32, 8)>>>(Wlm,   Wlh, Wll, H_, V_);

    embed_split_kernel<<<MTOK, 256>>>(ids, tab, x, xh, xl);
    gemm_mma<<<dim3(MTOK / 128, QKVZ_N / 128), 256, GEMM_SMEM>>>(
        MTOK, QKVZ_N, H_, xh, xl, Wqh, Wql, qkvz, (bf16*)0, (bf16*)0);
    sgemm128<<<dim3(1, MTOK / 128), 256>>>(MTOK, 64, H_, x, Wba, ba);
    conv_silu_kernel<<<(MTOK * CDIM) / 256, 256>>>(qkvz, cw, cb, conv);
    norm_qk_kernel<<<MTOK * HK_, 128>>>(conv, qn, kn);
    gates_kernel<<<MTOK, 32>>>(ba, A_log, dtb, gg, bb);
    scan_kernel<<<B_ * HV_ * 2, 256>>>(qn, kn, conv, gg, bb, o);
    gated_norm_split<<<MTOK * HV_, 128>>>(o, qkvz, nw, oh, ol);
    gemm_mma<<<dim3(MTOK / 128, H_ / 128), 256, GEMM_SMEM>>>(
        MTOK, H_, VDIM, oh, ol, Woh, Wol, (float*)0, hh, hl);
    gemm_mma<<<dim3(MTOK / 128, V_ / 128), 256, GEMM_SMEM>>>(
        MTOK, V_, H_, hh, hl, Wlh, Wll, out, (bf16*)0, (bf16*)0);
}

// round 8
// speedup vs baseline: 4.4831x; 1.2962x over previous
#include <cuda_runtime.h>
#include <cuda_fp16.h>
#include <cstdint>
#include <cstddef>

#define B_    2
#define T_    1024
#define MTOK  2048
#define H_    2048
#define V_    32000
#define HK_   16
#define HV_   32
#define DK_   128
#define DV_   128
#define QKDIM 2048
#define VDIM  4096
#define CDIM  8192
#define QKVZ_N 12288

typedef __half fp16;

// ==================== scratch ====================
__device__ float g_x[MTOK * H_];
__device__ float g_qkvz[(size_t)MTOK * QKVZ_N];
__device__ float g_ba[MTOK * 64];
__device__ float g_conv[(size_t)MTOK * CDIM];
__device__ float g_qn[MTOK * QKDIM];
__device__ float g_kn[MTOK * QKDIM];
__device__ float g_g[MTOK * HV_];
__device__ float g_beta[MTOK * HV_];
__device__ float g_o[(size_t)MTOK * VDIM];

// fp16 hi/lo activation limbs [M,K]; fp16 hi-only transposed weights [N,K]
__device__ fp16 g_xh[MTOK * H_],  g_xl[MTOK * H_];
__device__ fp16 g_oh[(size_t)MTOK * VDIM], g_ol[(size_t)MTOK * VDIM];
__device__ fp16 g_hh[MTOK * H_],  g_hl[MTOK * H_];
__device__ fp16 g_Wqh[(size_t)QKVZ_N * H_];
__device__ fp16 g_Woh[(size_t)H_ * VDIM];
__device__ fp16 g_Wlh[(size_t)V_ * H_];

// ==================== helpers ====================
__device__ __forceinline__ uint32_t smem_u32(const void* p) {
    uint32_t a;
    asm("{ .reg .u64 t; cvta.to.shared.u64 t, %1; cvt.u32.u64 %0, t; }" : "=r"(a) : "l"(p));
    return a;
}
__device__ __forceinline__ void cpa16(uint32_t dst, const void* src) {
    asm volatile("cp.async.cg.shared.global [%0], [%1], 16;" :: "r"(dst), "l"(src) : "memory");
}
#define CPA_COMMIT() asm volatile("cp.async.commit_group;" ::: "memory")
#define CPA_WAIT2()  asm volatile("cp.async.wait_group 2;" ::: "memory")
#define CPA_WAIT1()  asm volatile("cp.async.wait_group 1;" ::: "memory")

__device__ __forceinline__ void ldm_x4(uint32_t* r, uint32_t addr) {
    asm volatile("ldmatrix.sync.aligned.m8n8.x4.shared.b16 {%0,%1,%2,%3}, [%4];"
                 : "=r"(r[0]), "=r"(r[1]), "=r"(r[2]), "=r"(r[3]) : "r"(addr));
}
__device__ __forceinline__ void mma16816(float* c, const uint32_t* a, const uint32_t* b) {
    asm volatile(
        "mma.sync.aligned.m16n8k16.row.col.f32.f16.f16.f32 "
        "{%0,%1,%2,%3}, {%4,%5,%6,%7}, {%8,%9}, {%0,%1,%2,%3};\n"
        : "+f"(c[0]), "+f"(c[1]), "+f"(c[2]), "+f"(c[3])
        : "r"(a[0]), "r"(a[1]), "r"(a[2]), "r"(a[3]), "r"(b[0]), "r"(b[1]));
}
#define SWZ(off) ((off) ^ (((off) >> 3) & 0x70))

__device__ __forceinline__ void split2(float v, fp16& h, fp16& l) {
    h = __float2half_rn(v);
    l = __float2half_rn(v - __half2float(h));
}

// ==================== 2-term fp16 mma.sync GEMM ====================
// C[M,N] = (Ah+Al)[M,K] @ Bh[N,K]^T. Block 128x128, BK=64, 3-stage cp.async,
// ldmatrix on SW128-swizzled smem, 256 threads (8 warps, 2m x 4n).
#define STG_BYTES 49152
#define O_AL 16384
#define O_BH 32768
#define GEMM_SMEM (3 * STG_BYTES + 1024)

__global__ __launch_bounds__(256, 1) void gemm_mma(
    int M, int N, int K,
    const fp16* __restrict__ Ah, const fp16* __restrict__ Al,
    const fp16* __restrict__ Bh,
    float* __restrict__ Cf, fp16* __restrict__ Chi, fp16* __restrict__ Clo) {
    extern __shared__ char dsm_raw[];
    uint32_t dbase = (smem_u32(dsm_raw) + 1023u) & ~1023u;

    int tid = threadIdx.x;
    int lane = tid & 31, wid = tid >> 5;
    int wm = wid >> 2, wn = wid & 3;                 // warp tile 64(m) x 32(n)
    int row0 = blockIdx.x << 7;                      // m fastest: weight-stripe L2 reuse
    int col0 = blockIdx.y << 7;

    int lrow = ((lane >> 3) & 1) * 8 + (lane & 7);
    int lbyte = (lane >> 4) * 16;
    int rowA = wm * 64 + lrow;
    int rowB = wn * 32 + lrow;

    float acc[4][4][4];
#pragma unroll
    for (int i = 0; i < 4; i++)
#pragma unroll
        for (int j = 0; j < 4; j++)
#pragma unroll
            for (int r = 0; r < 4; r++) acc[i][j][r] = 0.f;

    int nk = K >> 6;

    auto load_stage = [&](int slot, int kc) {
        uint32_t stg = dbase + slot * STG_BYTES;
        int k0 = kc << 6;
#pragma unroll
        for (int i = 0; i < 4; i++) {
            int c = tid + (i << 8);
            int row = c >> 3, c8 = c & 7;
            uint32_t sw = SWZ((uint32_t)(row * 128 + c8 * 16));
            size_t ga = (size_t)(row0 + row) * K + k0 + c8 * 8;
            size_t gb = (size_t)(col0 + row) * K + k0 + c8 * 8;
            cpa16(stg + sw, Ah + ga);
            cpa16(stg + O_AL + sw, Al + ga);
            cpa16(stg + O_BH + sw, Bh + gb);
        }
    };

    load_stage(0, 0); CPA_COMMIT();
    load_stage(1, 1); CPA_COMMIT();
    load_stage(2, 2); CPA_COMMIT();

    for (int kc = 0; kc < nk; kc++) {
        CPA_WAIT2();
        __syncthreads();
        uint32_t stg = dbase + (kc % 3) * STG_BYTES;
#pragma unroll
        for (int kk = 0; kk < 4; kk++) {
            uint32_t fah[4][4], fal[4][4], fbh[4][2];
#pragma unroll
            for (int mi = 0; mi < 4; mi++) {
                uint32_t off = SWZ((uint32_t)((rowA + mi * 16) * 128 + kk * 32 + lbyte));
                ldm_x4(fah[mi], stg + off);
                ldm_x4(fal[mi], stg + O_AL + off);
            }
#pragma unroll
            for (int nj = 0; nj < 2; nj++) {
                uint32_t off = SWZ((uint32_t)((rowB + nj * 16) * 128 + kk * 32 + lbyte));
                uint32_t rh[4];
                ldm_x4(rh, stg + O_BH + off);
                fbh[nj * 2][0] = rh[0]; fbh[nj * 2][1] = rh[2];
                fbh[nj * 2 + 1][0] = rh[1]; fbh[nj * 2 + 1][1] = rh[3];
            }
#pragma unroll
            for (int mi = 0; mi < 4; mi++)
#pragma unroll
                for (int ni = 0; ni < 4; ni++) {
                    mma16816(acc[mi][ni], fah[mi], fbh[ni]);
                    mma16816(acc[mi][ni], fal[mi], fbh[ni]);
                }
        }
        __syncthreads();
        if (kc + 3 < nk) load_stage(kc % 3, kc + 3);
        CPA_COMMIT();
    }

    // epilogue
    int g = lane >> 2, tig = lane & 3;
#pragma unroll
    for (int mi = 0; mi < 4; mi++) {
        int r = row0 + wm * 64 + mi * 16 + g;
#pragma unroll
        for (int ni = 0; ni < 4; ni++) {
            int c = col0 + wn * 32 + ni * 8 + 2 * tig;
            float a0 = acc[mi][ni][0], a1 = acc[mi][ni][1];
            float a2 = acc[mi][ni][2], a3 = acc[mi][ni][3];
            if (Cf) {
                *reinterpret_cast<float2*>(Cf + (size_t)r * N + c) = make_float2(a0, a1);
                *reinterpret_cast<float2*>(Cf + (size_t)(r + 8) * N + c) = make_float2(a2, a3);
            }
            if (Chi) {
                fp16 h0, h1, h2, h3, l0, l1, l2, l3;
                split2(a0, h0, l0); split2(a1, h1, l1);
                split2(a2, h2, l2); split2(a3, h3, l3);
                *reinterpret_cast<__half2*>(Chi + (size_t)r * N + c) = __halves2half2(h0, h1);
                *reinterpret_cast<__half2*>(Chi + (size_t)(r + 8) * N + c) = __halves2half2(h2, h3);
                *reinterpret_cast<__half2*>(Clo + (size_t)r * N + c) = __halves2half2(l0, l1);
                *reinterpret_cast<__half2*>(Clo + (size_t)(r + 8) * N + c) = __halves2half2(l2, l3);
            }
        }
    }
}

// ==================== embed + split ====================
__global__ void embed_split_kernel(const int* __restrict__ ids, const float* __restrict__ tab,
                                   float* __restrict__ x, fp16* __restrict__ xh,
                                   fp16* __restrict__ xl) {
    int m = blockIdx.x;
    int id = ids[m];
    const float4* src = reinterpret_cast<const float4*>(tab + (size_t)id * H_);
    float4* dst = reinterpret_cast<float4*>(x + (size_t)m * H_);
    __half2* ph = reinterpret_cast<__half2*>(xh) + (size_t)m * (H_ / 2);
    __half2* pl = reinterpret_cast<__half2*>(xl) + (size_t)m * (H_ / 2);
    for (int i = threadIdx.x; i < H_ / 4; i += blockDim.x) {
        float4 v = src[i];
        dst[i] = v;
        fp16 h0, h1, h2, h3, l0, l1, l2, l3;
        split2(v.x, h0, l0); split2(v.y, h1, l1);
        split2(v.z, h2, l2); split2(v.w, h3, l3);
        ph[2 * i + 0] = __halves2half2(h0, h1);
        ph[2 * i + 1] = __halves2half2(h2, h3);
        pl[2 * i + 0] = __halves2half2(l0, l1);
        pl[2 * i + 1] = __halves2half2(l2, l3);
    }
}

// ==================== transpose weights to fp16: W[K,N] -> Th[N,K] ====================
__global__ __launch_bounds__(256) void tsplit_kernel(const float* __restrict__ W,
                                                     fp16* __restrict__ Th,
                                                     int K, int N) {
    __shared__ float tile[32][33];
    int kb = blockIdx.x << 5, nb = blockIdx.y << 5;
    int tx = threadIdx.x, ty = threadIdx.y;  // (32, 8)
#pragma unroll
    for (int j = 0; j < 4; j++)
        tile[ty + j * 8][tx] = W[(size_t)(kb + ty + j * 8) * N + nb + tx];
    __syncthreads();
#pragma unroll
    for (int j = 0; j < 4; j++) {
        float v = tile[tx][ty + j * 8];
        Th[(size_t)(nb + ty + j * 8) * K + kb + tx] = __float2half_rn(v);
    }
}

// ==================== small fp32 SGEMM (ba: N=64) ====================
__global__ __launch_bounds__(256) void sgemm128(int M, int N, int K,
                                                const float* __restrict__ A,
                                                const float* __restrict__ Bm,
                                                float* __restrict__ C) {
    __shared__ float As[8][128];
    __shared__ float Bs[8][128];
    int tid = threadIdx.x;
    int cRow = blockIdx.y << 7;
    int cCol = blockIdx.x << 7;
    int aRow = tid >> 1, aCol = (tid & 1) << 2;
    int bRow = tid >> 5, bCol = (tid & 31) << 2;
    int tr = (tid >> 4) << 3, tc = (tid & 15) << 3;
    float acc[8][8];
#pragma unroll
    for (int i = 0; i < 8; i++)
#pragma unroll
        for (int j = 0; j < 8; j++) acc[i][j] = 0.f;
    const float* aptr = A + (size_t)(cRow + aRow) * K + aCol;
    bool bok = (cCol + bCol) < N;
    const float* bptr = Bm + (size_t)bRow * N + cCol + bCol;
    for (int k0 = 0; k0 < K; k0 += 8) {
        float4 av = *reinterpret_cast<const float4*>(aptr + k0);
        As[aCol + 0][aRow] = av.x; As[aCol + 1][aRow] = av.y;
        As[aCol + 2][aRow] = av.z; As[aCol + 3][aRow] = av.w;
        float4 bv = make_float4(0.f, 0.f, 0.f, 0.f);
        if (bok) bv = *reinterpret_cast<const float4*>(bptr + (size_t)k0 * N);
        *reinterpret_cast<float4*>(&Bs[bRow][bCol]) = bv;
        __syncthreads();
#pragma unroll
        for (int kk = 0; kk < 8; kk++) {
            float4 a0 = *reinterpret_cast<const float4*>(&As[kk][tr]);
            float4 a1 = *reinterpret_cast<const float4*>(&As[kk][tr + 4]);
            float4 b0 = *reinterpret_cast<const float4*>(&Bs[kk][tc]);
            float4 b1 = *reinterpret_cast<const float4*>(&Bs[kk][tc + 4]);
            float ar[8] = {a0.x, a0.y, a0.z, a0.w, a1.x, a1.y, a1.z, a1.w};
            float br[8] = {b0.x, b0.y, b0.z, b0.w, b1.x, b1.y, b1.z, b1.w};
#pragma unroll
            for (int i = 0; i < 8; i++)
#pragma unroll
                for (int j = 0; j < 8; j++) acc[i][j] += ar[i] * br[j];
        }
        __syncthreads();
    }
#pragma unroll
    for (int i = 0; i < 8; i++) {
        size_t r = (size_t)(cRow + tr + i);
#pragma unroll
        for (int j = 0; j < 8; j += 4) {
            int c = cCol + tc + j;
            if (c < N)
                *reinterpret_cast<float4*>(C + r * N + c) =
                    make_float4(acc[i][j], acc[i][j + 1], acc[i][j + 2], acc[i][j + 3]);
        }
    }
}

// ==================== conv + silu ====================
__global__ void conv_silu_kernel(const float* __restrict__ qkvz, const float* __restrict__ cw,
                                 const float* __restrict__ cb, float* __restrict__ out) {
    int idx = blockIdx.x * blockDim.x + threadIdx.x;
    int c = idx & (CDIM - 1);
    int m = idx >> 13;
    int t = m & (T_ - 1);
    const float* w = cw + c * 4;
    float s = cb[c];
#pragma unroll
    for (int j = 0; j < 4; j++) {
        int tt = t - 3 + j;
        if (tt >= 0) s += w[j] * qkvz[(size_t)(m - 3 + j) * QKVZ_N + c];
    }
    out[(size_t)m * CDIM + c] = s / (1.f + expf(-s));
}

// ==================== l2norm q/k ====================
__global__ __launch_bounds__(128) void norm_qk_kernel(const float* __restrict__ conv,
                                                      float* __restrict__ qn,
                                                      float* __restrict__ kn) {
    int m = blockIdx.x >> 4;
    int hh = blockIdx.x & 15;
    int i = threadIdx.x;
    const float* qr = conv + (size_t)m * CDIM + hh * DK_;
    const float* kr = conv + (size_t)m * CDIM + QKDIM + hh * DK_;
    float qv = qr[i], kv = kr[i];
    float q2 = qv * qv, k2 = kv * kv;
#pragma unroll
    for (int off = 16; off; off >>= 1) {
        q2 += __shfl_xor_sync(0xffffffffu, q2, off);
        k2 += __shfl_xor_sync(0xffffffffu, k2, off);
    }
    __shared__ float shq[4], shk[4];
    if ((i & 31) == 0) { shq[i >> 5] = q2; shk[i >> 5] = k2; }
    __syncthreads();
    float sq = shq[0] + shq[1] + shq[2] + shq[3];
    float sk = shk[0] + shk[1] + shk[2] + shk[3];
    qn[(size_t)m * QKDIM + hh * DK_ + i] = qv * rsqrtf(sq + 1e-6f) * 0.08838834764831845f;
    kn[(size_t)m * QKDIM + hh * DK_ + i] = kv * rsqrtf(sk + 1e-6f);
}

// ==================== gates ====================
__global__ void gates_kernel(const float* __restrict__ ba, const float* __restrict__ A_log,
                             const float* __restrict__ dtb, float* __restrict__ g,
                             float* __restrict__ beta) {
    int m = blockIdx.x;
    int h = threadIdx.x;
    float bv = ba[m * 64 + h];
    float av = ba[m * 64 + 32 + h];
    beta[m * HV_ + h] = 1.f / (1.f + expf(-bv));
    float x = av + dtb[h];
    float sp = (x > 20.f) ? x : log1pf(expf(x));
    g[m * HV_ + h] = -expf(A_log[h]) * sp;
}

// ==================== scan (cp.async prefetch pipeline) ====================
__global__ __launch_bounds__(256) void scan_kernel(const float* __restrict__ qn,
                                                   const float* __restrict__ kn,
                                                   const float* __restrict__ conv,
                                                   const float* __restrict__ gg,
                                                   const float* __restrict__ bb,
                                                   float* __restrict__ o) {
    int bid = blockIdx.x;
    int split = bid & 1;
    int h = (bid >> 1) & 31;
    int b = bid >> 6;
    int kh = h >> 1;
    int v0 = split * 64;
    int tid = threadIdx.x;
    int vloc = tid >> 2;
    int kseg = tid & 3;
    int k0 = kseg * 32;

    __shared__ float sk[3][128], sq[3][128];

    float S[32];
#pragma unroll
    for (int i = 0; i < 32; i++) S[i] = 0.f;

    const float* qrow = qn + (size_t)(b * T_) * QKDIM + kh * DK_;
    const float* krow = kn + (size_t)(b * T_) * QKDIM + kh * DK_;
    const float* vrow = conv + (size_t)(b * T_) * CDIM + 2 * QKDIM + h * DV_ + v0 + vloc;
    const float* grow = gg + (b * T_) * HV_ + h;
    const float* brow = bb + (b * T_) * HV_ + h;
    float* orow = o + (size_t)(b * T_) * VDIM + h * DV_ + v0 + vloc;

    // k/q row prefetch via cp.async: threads 0-31 -> k chunks, 32-63 -> q chunks
    auto prefetch = [&](int t) {
        if (t < T_) {
            int buf = t % 3;
            if (tid < 32)
                cpa16(smem_u32(&sk[buf][tid * 4]), krow + (size_t)t * QKDIM + tid * 4);
            else if (tid < 64)
                cpa16(smem_u32(&sq[buf][(tid - 32) * 4]), qrow + (size_t)t * QKDIM + (tid - 32) * 4);
        }
        CPA_COMMIT();
    };

    prefetch(0);
    // distance-2 scalar prefetch for v, g, beta
    float vt0 = vrow[0], gt0 = grow[0], bt0 = brow[0];
    float vt1 = vrow[CDIM], gt1 = grow[HV_], bt1 = brow[HV_];

    for (int t = 0; t < T_; t++) {
        prefetch(t + 1);
        float vt2 = 0.f, gt2 = 0.f, bt2 = 0.f;
        if (t + 2 < T_) {
            vt2 = vrow[(size_t)(t + 2) * CDIM];
            gt2 = grow[(size_t)(t + 2) * HV_];
            bt2 = brow[(size_t)(t + 2) * HV_];
        }
        CPA_WAIT1();
        __syncthreads();
        int buf = t % 3;
        float decay = expf(gt0);
        float pkv = 0.f;
#pragma unroll
        for (int i = 0; i < 32; i++) {
            float s = S[i] * decay;
            S[i] = s;
            pkv += sk[buf][k0 + i] * s;
        }
        pkv += __shfl_xor_sync(0xffffffffu, pkv, 1);
        pkv += __shfl_xor_sync(0xffffffffu, pkv, 2);
        float delta = (vt0 - pkv) * bt0;
        float po = 0.f;
#pragma unroll
        for (int i = 0; i < 32; i++) {
            float s = S[i] + sk[buf][k0 + i] * delta;
            S[i] = s;
            po += sq[buf][k0 + i] * s;
        }
        po += __shfl_xor_sync(0xffffffffu, po, 1);
        po += __shfl_xor_sync(0xffffffffu, po, 2);
        if (kseg == 0) orow[(size_t)t * VDIM] = po;
        vt0 = vt1; gt0 = gt1; bt0 = bt1;
        vt1 = vt2; gt1 = gt2; bt1 = bt2;
    }
}

// ==================== gated RMSNorm + fp16 split ====================
__global__ __launch_bounds__(128) void gated_norm_split(const float* __restrict__ o,
                                                        const float* __restrict__ qkvz,
                                                        const float* __restrict__ nw,
                                                        fp16* __restrict__ oh,
                                                        fp16* __restrict__ ol) {
    int m = blockIdx.x >> 5;
    int h = blockIdx.x & 31;
    int i = threadIdx.x;
    size_t oidx = (size_t)m * VDIM + h * DV_ + i;
    float ov = o[oidx];
    float zv = qkvz[(size_t)m * QKVZ_N + 2 * QKDIM + VDIM + h * DV_ + i];
    float gv = ov * (zv / (1.f + expf(-zv)));
    float s2 = gv * gv;
#pragma unroll
    for (int off = 16; off; off >>= 1) s2 += __shfl_xor_sync(0xffffffffu, s2, off);
    __shared__ float sh[4];
    if ((i & 31) == 0) sh[i >> 5] = s2;
    __syncthreads();
    float mean = (sh[0] + sh[1] + sh[2] + sh[3]) * (1.f / 128.f);
    float val = gv * rsqrtf(mean + 1e-6f) * nw[i];
    fp16 hh, ll;
    split2(val, hh, ll);
    oh[oidx] = hh;
    ol[oidx] = ll;
}

// ==================== launch ====================
extern "C" void kernel_launch(void* const* d_in, const int* in_sizes, int n_in,
                              void* d_out, int out_size) {
    const int*   ids   = (const int*)d_in[0];
    const float* tab   = (const float*)d_in[1];
    const float* Wqkvz = (const float*)d_in[2];
    const float* Wba   = (const float*)d_in[3];
    const float* cw    = (const float*)d_in[4];
    const float* cb    = (const float*)d_in[5];
    const float* A_log = (const float*)d_in[6];
    const float* dtb   = (const float*)d_in[7];
    const float* nw    = (const float*)d_in[8];
    const float* Wout  = (const float*)d_in[9];
    const float* Wlm   = (const float*)d_in[10];
    float* out = (float*)d_out;

    cudaFuncSetAttribute(gemm_mma, cudaFuncAttributeMaxDynamicSharedMemorySize, GEMM_SMEM);

    float *x, *qkvz, *ba, *conv, *qn, *kn, *gg, *bb, *o;
    cudaGetSymbolAddress((void**)&x,    g_x);
    cudaGetSymbolAddress((void**)&qkvz, g_qkvz);
    cudaGetSymbolAddress((void**)&ba,   g_ba);
    cudaGetSymbolAddress((void**)&conv, g_conv);
    cudaGetSymbolAddress((void**)&qn,   g_qn);
    cudaGetSymbolAddress((void**)&kn,   g_kn);
    cudaGetSymbolAddress((void**)&gg,   g_g);
    cudaGetSymbolAddress((void**)&bb,   g_beta);
    cudaGetSymbolAddress((void**)&o,    g_o);

    fp16 *xh, *xl, *oh, *ol, *hh, *hl, *Wqh, *Woh, *Wlh;
    cudaGetSymbolAddress((void**)&xh, g_xh);  cudaGetSymbolAddress((void**)&xl, g_xl);
    cudaGetSymbolAddress((void**)&oh, g_oh);  cudaGetSymbolAddress((void**)&ol, g_ol);
    cudaGetSymbolAddress((void**)&hh, g_hh);  cudaGetSymbolAddress((void**)&hl, g_hl);
    cudaGetSymbolAddress((void**)&Wqh, g_Wqh);
    cudaGetSymbolAddress((void**)&Woh, g_Woh);
    cudaGetSymbolAddress((void**)&Wlh, g_Wlh);

    // weight transpose to fp16: W[K,N] -> [N,K]
    tsplit_kernel<<<dim3(H_ / 32, QKVZ_N / 32), dim3(32, 8)>>>(Wqkvz, Wqh, H_, QKVZ_N);
    tsplit_kernel<<<dim3(VDIM / 32, H_ / 32),   dim3(32, 8)>>>(Wout,  Woh, VDIM, H_);
    tsplit_kernel<<<dim3(H_ / 32, V_ / 32),     dim3(32, 8)>>>(Wlm,   Wlh, H_, V_);

    embed_split_kernel<<<MTOK, 256>>>(ids, tab, x, xh, xl);
    gemm_mma<<<dim3(MTOK / 128, QKVZ_N / 128), 256, GEMM_SMEM>>>(
        MTOK, QKVZ_N, H_, xh, xl, Wqh, qkvz, (fp16*)0, (fp16*)0);
    sgemm128<<<dim3(1, MTOK / 128), 256>>>(MTOK, 64, H_, x, Wba, ba);
    conv_silu_kernel<<<(MTOK * CDIM) / 256, 256>>>(qkvz, cw, cb, conv);
    norm_qk_kernel<<<MTOK * HK_, 128>>>(conv, qn, kn);
    gates_kernel<<<MTOK, 32>>>(ba, A_log, dtb, gg, bb);
    scan_kernel<<<B_ * HV_ * 2, 256>>>(qn, kn, conv, gg, bb, o);
    gated_norm_split<<<MTOK * HV_, 128>>>(o, qkvz, nw, oh, ol);
    gemm_mma<<<dim3(MTOK / 128, H_ / 128), 256, GEMM_SMEM>>>(
        MTOK, H_, VDIM, oh, ol, Woh, (float*)0, hh, hl);
    gemm_mma<<<dim3(MTOK / 128, V_ / 128), 256, GEMM_SMEM>>>(
        MTOK, V_, H_, hh, hl, Wlh, out, (fp16*)0, (fp16*)0);
}

// round 9
// speedup vs baseline: 5.3601x; 1.1956x over previous
#include <cuda_runtime.h>
#include <cuda_fp16.h>
#include <cstdint>
#include <cstddef>

#define B_    2
#define T_    1024
#define MTOK  2048
#define H_    2048
#define V_    32000
#define HK_   16
#define HV_   32
#define DK_   128
#define DV_   128
#define QKDIM 2048
#define VDIM  4096
#define CDIM  8192
#define QKVZ_N 12288

typedef __half fp16;

// ==================== scratch ====================
__device__ float g_x[MTOK * H_];
__device__ float g_qkvz[(size_t)MTOK * QKVZ_N];
__device__ float g_ba[MTOK * 64];
__device__ float g_conv[(size_t)MTOK * CDIM];
__device__ float g_qn[MTOK * QKDIM];
__device__ float g_kn[MTOK * QKDIM];
__device__ float g_g[MTOK * HV_];
__device__ float g_beta[MTOK * HV_];
__device__ float g_o[(size_t)MTOK * VDIM];

__device__ fp16 g_xh[MTOK * H_],  g_xl[MTOK * H_];
__device__ fp16 g_oh[(size_t)MTOK * VDIM], g_ol[(size_t)MTOK * VDIM];
__device__ fp16 g_hh[MTOK * H_];
__device__ fp16 g_Wqh[(size_t)QKVZ_N * H_];
__device__ fp16 g_Woh[(size_t)H_ * VDIM];
__device__ fp16 g_Wlh[(size_t)V_ * H_];

// ==================== helpers ====================
__device__ __forceinline__ uint32_t smem_u32(const void* p) {
    uint32_t a;
    asm("{ .reg .u64 t; cvta.to.shared.u64 t, %1; cvt.u32.u64 %0, t; }" : "=r"(a) : "l"(p));
    return a;
}
__device__ __forceinline__ void cpa16(uint32_t dst, const void* src) {
    asm volatile("cp.async.cg.shared.global [%0], [%1], 16;" :: "r"(dst), "l"(src) : "memory");
}
#define CPA_COMMIT() asm volatile("cp.async.commit_group;" ::: "memory")
#define CPA_WAIT2()  asm volatile("cp.async.wait_group 2;" ::: "memory")
#define CPA_WAIT1()  asm volatile("cp.async.wait_group 1;" ::: "memory")

__device__ __forceinline__ void ldm_x4(uint32_t* r, uint32_t addr) {
    asm volatile("ldmatrix.sync.aligned.m8n8.x4.shared.b16 {%0,%1,%2,%3}, [%4];"
                 : "=r"(r[0]), "=r"(r[1]), "=r"(r[2]), "=r"(r[3]) : "r"(addr));
}
__device__ __forceinline__ void mma16816(float* c, const uint32_t* a, const uint32_t* b) {
    asm volatile(
        "mma.sync.aligned.m16n8k16.row.col.f32.f16.f16.f32 "
        "{%0,%1,%2,%3}, {%4,%5,%6,%7}, {%8,%9}, {%0,%1,%2,%3};\n"
        : "+f"(c[0]), "+f"(c[1]), "+f"(c[2]), "+f"(c[3])
        : "r"(a[0]), "r"(a[1]), "r"(a[2]), "r"(a[3]), "r"(b[0]), "r"(b[1]));
}
#define SWZ(off) ((off) ^ (((off) >> 3) & 0x70))

__device__ __forceinline__ void split2(float v, fp16& h, fp16& l) {
    h = __float2half_rn(v);
    l = __float2half_rn(v - __half2float(h));
}

// ==================== fp16 mma.sync GEMM (1 or 2 A-limb terms) ====================
// C[M,N] = (Ah[+Al])[M,K] @ Bh[N,K]^T. Block 128x128, BK=64, 3-stage cp.async,
// ldmatrix on SW128-swizzled smem, fragment double-buffering, 256 threads.
#define STG_BYTES 49152
#define O_AL 16384
#define O_BH 32768
#define GEMM_SMEM (3 * STG_BYTES + 1024)

template <bool HAS_AL>
__global__ __launch_bounds__(256, 1) void gemm_mma(
    int M, int N, int K,
    const fp16* __restrict__ Ah, const fp16* __restrict__ Al,
    const fp16* __restrict__ Bh,
    float* __restrict__ Cf, fp16* __restrict__ Chi, fp16* __restrict__ Clo) {
    extern __shared__ char dsm_raw[];
    uint32_t dbase = (smem_u32(dsm_raw) + 1023u) & ~1023u;

    int tid = threadIdx.x;
    int lane = tid & 31, wid = tid >> 5;
    int wm = wid >> 2, wn = wid & 3;                 // warp tile 64(m) x 32(n)
    int row0 = blockIdx.x << 7;                      // m fastest: weight-stripe L2 reuse
    int col0 = blockIdx.y << 7;

    int lrow = ((lane >> 3) & 1) * 8 + (lane & 7);
    int lbyte = (lane >> 4) * 16;
    int rowA = wm * 64 + lrow;
    int rowB = wn * 32 + lrow;

    float acc[4][4][4];
#pragma unroll
    for (int i = 0; i < 4; i++)
#pragma unroll
        for (int j = 0; j < 4; j++)
#pragma unroll
            for (int r = 0; r < 4; r++) acc[i][j][r] = 0.f;

    int nk = K >> 6;

    auto load_stage = [&](int slot, int kc) {
        uint32_t stg = dbase + slot * STG_BYTES;
        int k0 = kc << 6;
#pragma unroll
        for (int i = 0; i < 4; i++) {
            int c = tid + (i << 8);
            int row = c >> 3, c8 = c & 7;
            uint32_t sw = SWZ((uint32_t)(row * 128 + c8 * 16));
            size_t ga = (size_t)(row0 + row) * K + k0 + c8 * 8;
            size_t gb = (size_t)(col0 + row) * K + k0 + c8 * 8;
            cpa16(stg + sw, Ah + ga);
            if (HAS_AL) cpa16(stg + O_AL + sw, Al + ga);
            cpa16(stg + O_BH + sw, Bh + gb);
        }
    };

    load_stage(0, 0); CPA_COMMIT();
    load_stage(1, 1); CPA_COMMIT();
    load_stage(2, 2); CPA_COMMIT();

    // fragment double buffers
    uint32_t fah[2][4][4], fal[2][4][4], fbh[2][4][2];

    auto loadfrag = [&](int buf, uint32_t stg, int kk) {
#pragma unroll
        for (int mi = 0; mi < 4; mi++) {
            uint32_t off = SWZ((uint32_t)((rowA + mi * 16) * 128 + kk * 32 + lbyte));
            ldm_x4(fah[buf][mi], stg + off);
            if (HAS_AL) ldm_x4(fal[buf][mi], stg + O_AL + off);
        }
#pragma unroll
        for (int nj = 0; nj < 2; nj++) {
            uint32_t off = SWZ((uint32_t)((rowB + nj * 16) * 128 + kk * 32 + lbyte));
            uint32_t rh[4];
            ldm_x4(rh, stg + O_BH + off);
            fbh[buf][nj * 2][0] = rh[0];     fbh[buf][nj * 2][1] = rh[2];
            fbh[buf][nj * 2 + 1][0] = rh[1]; fbh[buf][nj * 2 + 1][1] = rh[3];
        }
    };

    for (int kc = 0; kc < nk; kc++) {
        CPA_WAIT2();
        __syncthreads();
        uint32_t stg = dbase + (kc % 3) * STG_BYTES;
        loadfrag(0, stg, 0);
#pragma unroll
        for (int kk = 0; kk < 4; kk++) {
            int cur = kk & 1;
            if (kk < 3) loadfrag(cur ^ 1, stg, kk + 1);
#pragma unroll
            for (int mi = 0; mi < 4; mi++)
#pragma unroll
                for (int ni = 0; ni < 4; ni++) {
                    mma16816(acc[mi][ni], fah[cur][mi], fbh[cur][ni]);
                    if (HAS_AL) mma16816(acc[mi][ni], fal[cur][mi], fbh[cur][ni]);
                }
        }
        __syncthreads();
        if (kc + 3 < nk) load_stage(kc % 3, kc + 3);
        CPA_COMMIT();
    }

    // epilogue
    int g = lane >> 2, tig = lane & 3;
#pragma unroll
    for (int mi = 0; mi < 4; mi++) {
        int r = row0 + wm * 64 + mi * 16 + g;
#pragma unroll
        for (int ni = 0; ni < 4; ni++) {
            int c = col0 + wn * 32 + ni * 8 + 2 * tig;
            float a0 = acc[mi][ni][0], a1 = acc[mi][ni][1];
            float a2 = acc[mi][ni][2], a3 = acc[mi][ni][3];
            if (Cf) {
                *reinterpret_cast<float2*>(Cf + (size_t)r * N + c) = make_float2(a0, a1);
                *reinterpret_cast<float2*>(Cf + (size_t)(r + 8) * N + c) = make_float2(a2, a3);
            }
            if (Chi) {
                fp16 h0 = __float2half_rn(a0), h1 = __float2half_rn(a1);
                fp16 h2 = __float2half_rn(a2), h3 = __float2half_rn(a3);
                *reinterpret_cast<__half2*>(Chi + (size_t)r * N + c) = __halves2half2(h0, h1);
                *reinterpret_cast<__half2*>(Chi + (size_t)(r + 8) * N + c) = __halves2half2(h2, h3);
                if (Clo) {
                    fp16 l0 = __float2half_rn(a0 - __half2float(h0));
                    fp16 l1 = __float2half_rn(a1 - __half2float(h1));
                    fp16 l2 = __float2half_rn(a2 - __half2float(h2));
                    fp16 l3 = __float2half_rn(a3 - __half2float(h3));
                    *reinterpret_cast<__half2*>(Clo + (size_t)r * N + c) = __halves2half2(l0, l1);
                    *reinterpret_cast<__half2*>(Clo + (size_t)(r + 8) * N + c) = __halves2half2(l2, l3);
                }
            }
        }
    }
}

// ==================== embed + split ====================
__global__ void embed_split_kernel(const int* __restrict__ ids, const float* __restrict__ tab,
                                   float* __restrict__ x, fp16* __restrict__ xh,
                                   fp16* __restrict__ xl) {
    int m = blockIdx.x;
    int id = ids[m];
    const float4* src = reinterpret_cast<const float4*>(tab + (size_t)id * H_);
    float4* dst = reinterpret_cast<float4*>(x + (size_t)m * H_);
    __half2* ph = reinterpret_cast<__half2*>(xh) + (size_t)m * (H_ / 2);
    __half2* pl = reinterpret_cast<__half2*>(xl) + (size_t)m * (H_ / 2);
    for (int i = threadIdx.x; i < H_ / 4; i += blockDim.x) {
        float4 v = src[i];
        dst[i] = v;
        fp16 h0, h1, h2, h3, l0, l1, l2, l3;
        split2(v.x, h0, l0); split2(v.y, h1, l1);
        split2(v.z, h2, l2); split2(v.w, h3, l3);
        ph[2 * i + 0] = __halves2half2(h0, h1);
        ph[2 * i + 1] = __halves2half2(h2, h3);
        pl[2 * i + 0] = __halves2half2(l0, l1);
        pl[2 * i + 1] = __halves2half2(l2, l3);
    }
}

// ==================== transpose weights to fp16: W[K,N] -> Th[N,K] ====================
__global__ __launch_bounds__(256) void tsplit_kernel(const float* __restrict__ W,
                                                     fp16* __restrict__ Th,
                                                     int K, int N) {
    __shared__ float tile[32][33];
    int kb = blockIdx.x << 5, nb = blockIdx.y << 5;
    int tx = threadIdx.x, ty = threadIdx.y;  // (32, 8)
#pragma unroll
    for (int j = 0; j < 4; j++)
        tile[ty + j * 8][tx] = W[(size_t)(kb + ty + j * 8) * N + nb + tx];
    __syncthreads();
#pragma unroll
    for (int j = 0; j < 4; j++) {
        float v = tile[tx][ty + j * 8];
        Th[(size_t)(nb + ty + j * 8) * K + kb + tx] = __float2half_rn(v);
    }
}

// ==================== small fp32 SGEMM (ba: N=64) ====================
__global__ __launch_bounds__(256) void sgemm128(int M, int N, int K,
                                                const float* __restrict__ A,
                                                const float* __restrict__ Bm,
                                                float* __restrict__ C) {
    __shared__ float As[8][128];
    __shared__ float Bs[8][128];
    int tid = threadIdx.x;
    int cRow = blockIdx.y << 7;
    int cCol = blockIdx.x << 7;
    int aRow = tid >> 1, aCol = (tid & 1) << 2;
    int bRow = tid >> 5, bCol = (tid & 31) << 2;
    int tr = (tid >> 4) << 3, tc = (tid & 15) << 3;
    float acc[8][8];
#pragma unroll
    for (int i = 0; i < 8; i++)
#pragma unroll
        for (int j = 0; j < 8; j++) acc[i][j] = 0.f;
    const float* aptr = A + (size_t)(cRow + aRow) * K + aCol;
    bool bok = (cCol + bCol) < N;
    const float* bptr = Bm + (size_t)bRow * N + cCol + bCol;
    for (int k0 = 0; k0 < K; k0 += 8) {
        float4 av = *reinterpret_cast<const float4*>(aptr + k0);
        As[aCol + 0][aRow] = av.x; As[aCol + 1][aRow] = av.y;
        As[aCol + 2][aRow] = av.z; As[aCol + 3][aRow] = av.w;
        float4 bv = make_float4(0.f, 0.f, 0.f, 0.f);
        if (bok) bv = *reinterpret_cast<const float4*>(bptr + (size_t)k0 * N);
        *reinterpret_cast<float4*>(&Bs[bRow][bCol]) = bv;
        __syncthreads();
#pragma unroll
        for (int kk = 0; kk < 8; kk++) {
            float4 a0 = *reinterpret_cast<const float4*>(&As[kk][tr]);
            float4 a1 = *reinterpret_cast<const float4*>(&As[kk][tr + 4]);
            float4 b0 = *reinterpret_cast<const float4*>(&Bs[kk][tc]);
            float4 b1 = *reinterpret_cast<const float4*>(&Bs[kk][tc + 4]);
            float ar[8] = {a0.x, a0.y, a0.z, a0.w, a1.x, a1.y, a1.z, a1.w};
            float br[8] = {b0.x, b0.y, b0.z, b0.w, b1.x, b1.y, b1.z, b1.w};
#pragma unroll
            for (int i = 0; i < 8; i++)
#pragma unroll
                for (int j = 0; j < 8; j++) acc[i][j] += ar[i] * br[j];
        }
        __syncthreads();
    }
#pragma unroll
    for (int i = 0; i < 8; i++) {
        size_t r = (size_t)(cRow + tr + i);
#pragma unroll
        for (int j = 0; j < 8; j += 4) {
            int c = cCol + tc + j;
            if (c < N)
                *reinterpret_cast<float4*>(C + r * N + c) =
                    make_float4(acc[i][j], acc[i][j + 1], acc[i][j + 2], acc[i][j + 3]);
        }
    }
}

// ==================== conv + silu ====================
__global__ void conv_silu_kernel(const float* __restrict__ qkvz, const float* __restrict__ cw,
                                 const float* __restrict__ cb, float* __restrict__ out) {
    int idx = blockIdx.x * blockDim.x + threadIdx.x;
    int c = idx & (CDIM - 1);
    int m = idx >> 13;
    int t = m & (T_ - 1);
    const float* w = cw + c * 4;
    float s = cb[c];
#pragma unroll
    for (int j = 0; j < 4; j++) {
        int tt = t - 3 + j;
        if (tt >= 0) s += w[j] * qkvz[(size_t)(m - 3 + j) * QKVZ_N + c];
    }
    out[(size_t)m * CDIM + c] = s / (1.f + expf(-s));
}

// ==================== l2norm q/k ====================
__global__ __launch_bounds__(128) void norm_qk_kernel(const float* __restrict__ conv,
                                                      float* __restrict__ qn,
                                                      float* __restrict__ kn) {
    int m = blockIdx.x >> 4;
    int hh = blockIdx.x & 15;
    int i = threadIdx.x;
    const float* qr = conv + (size_t)m * CDIM + hh * DK_;
    const float* kr = conv + (size_t)m * CDIM + QKDIM + hh * DK_;
    float qv = qr[i], kv = kr[i];
    float q2 = qv * qv, k2 = kv * kv;
#pragma unroll
    for (int off = 16; off; off >>= 1) {
        q2 += __shfl_xor_sync(0xffffffffu, q2, off);
        k2 += __shfl_xor_sync(0xffffffffu, k2, off);
    }
    __shared__ float shq[4], shk[4];
    if ((i & 31) == 0) { shq[i >> 5] = q2; shk[i >> 5] = k2; }
    __syncthreads();
    float sq = shq[0] + shq[1] + shq[2] + shq[3];
    float sk = shk[0] + shk[1] + shk[2] + shk[3];
    qn[(size_t)m * QKDIM + hh * DK_ + i] = qv * rsqrtf(sq + 1e-6f) * 0.08838834764831845f;
    kn[(size_t)m * QKDIM + hh * DK_ + i] = kv * rsqrtf(sk + 1e-6f);
}

// ==================== gates ====================
__global__ void gates_kernel(const float* __restrict__ ba, const float* __restrict__ A_log,
                             const float* __restrict__ dtb, float* __restrict__ g,
                             float* __restrict__ beta) {
    int m = blockIdx.x;
    int h = threadIdx.x;
    float bv = ba[m * 64 + h];
    float av = ba[m * 64 + 32 + h];
    beta[m * HV_ + h] = 1.f / (1.f + expf(-bv));
    float x = av + dtb[h];
    float sp = (x > 20.f) ? x : log1pf(expf(x));
    g[m * HV_ + h] = -expf(A_log[h]) * sp;
}

// ==================== scan (cp.async prefetch pipeline) ====================
__global__ __launch_bounds__(256) void scan_kernel(const float* __restrict__ qn,
                                                   const float* __restrict__ kn,
                                                   const float* __restrict__ conv,
                                                   const float* __restrict__ gg,
                                                   const float* __restrict__ bb,
                                                   float* __restrict__ o) {
    int bid = blockIdx.x;
    int split = bid & 1;
    int h = (bid >> 1) & 31;
    int b = bid >> 6;
    int kh = h >> 1;
    int v0 = split * 64;
    int tid = threadIdx.x;
    int vloc = tid >> 2;
    int kseg = tid & 3;
    int k0 = kseg * 32;

    __shared__ float sk[3][128], sq[3][128];

    float S[32];
#pragma unroll
    for (int i = 0; i < 32; i++) S[i] = 0.f;

    const float* qrow = qn + (size_t)(b * T_) * QKDIM + kh * DK_;
    const float* krow = kn + (size_t)(b * T_) * QKDIM + kh * DK_;
    const float* vrow = conv + (size_t)(b * T_) * CDIM + 2 * QKDIM + h * DV_ + v0 + vloc;
    const float* grow = gg + (b * T_) * HV_ + h;
    const float* brow = bb + (b * T_) * HV_ + h;
    float* orow = o + (size_t)(b * T_) * VDIM + h * DV_ + v0 + vloc;

    auto prefetch = [&](int t) {
        if (t < T_) {
            int buf = t % 3;
            if (tid < 32)
                cpa16(smem_u32(&sk[buf][tid * 4]), krow + (size_t)t * QKDIM + tid * 4);
            else if (tid < 64)
                cpa16(smem_u32(&sq[buf][(tid - 32) * 4]), qrow + (size_t)t * QKDIM + (tid - 32) * 4);
        }
        CPA_COMMIT();
    };

    prefetch(0);
    float vt0 = vrow[0], gt0 = grow[0], bt0 = brow[0];
    float vt1 = vrow[CDIM], gt1 = grow[HV_], bt1 = brow[HV_];

    for (int t = 0; t < T_; t++) {
        prefetch(t + 1);
        float vt2 = 0.f, gt2 = 0.f, bt2 = 0.f;
        if (t + 2 < T_) {
            vt2 = vrow[(size_t)(t + 2) * CDIM];
            gt2 = grow[(size_t)(t + 2) * HV_];
            bt2 = brow[(size_t)(t + 2) * HV_];
        }
        CPA_WAIT1();
        __syncthreads();
        int buf = t % 3;
        float decay = expf(gt0);
        float pkv = 0.f;
#pragma unroll
        for (int i = 0; i < 32; i++) {
            float s = S[i] * decay;
            S[i] = s;
            pkv += sk[buf][k0 + i] * s;
        }
        pkv += __shfl_xor_sync(0xffffffffu, pkv, 1);
        pkv += __shfl_xor_sync(0xffffffffu, pkv, 2);
        float delta = (vt0 - pkv) * bt0;
        float po = 0.f;
#pragma unroll
        for (int i = 0; i < 32; i++) {
            float s = S[i] + sk[buf][k0 + i] * delta;
            S[i] = s;
            po += sq[buf][k0 + i] * s;
        }
        po += __shfl_xor_sync(0xffffffffu, po, 1);
        po += __shfl_xor_sync(0xffffffffu, po, 2);
        if (kseg == 0) orow[(size_t)t * VDIM] = po;
        vt0 = vt1; gt0 = gt1; bt0 = bt1;
        vt1 = vt2; gt1 = gt2; bt1 = bt2;
    }
}

// ==================== gated RMSNorm + fp16 split ====================
__global__ __launch_bounds__(128) void gated_norm_split(const float* __restrict__ o,
                                                        const float* __restrict__ qkvz,
                                                        const float* __restrict__ nw,
                                                        fp16* __restrict__ oh,
                                                        fp16* __restrict__ ol) {
    int m = blockIdx.x >> 5;
    int h = blockIdx.x & 31;
    int i = threadIdx.x;
    size_t oidx = (size_t)m * VDIM + h * DV_ + i;
    float ov = o[oidx];
    float zv = qkvz[(size_t)m * QKVZ_N + 2 * QKDIM + VDIM + h * DV_ + i];
    float gv = ov * (zv / (1.f + expf(-zv)));
    float s2 = gv * gv;
#pragma unroll
    for (int off = 16; off; off >>= 1) s2 += __shfl_xor_sync(0xffffffffu, s2, off);
    __shared__ float sh[4];
    if ((i & 31) == 0) sh[i >> 5] = s2;
    __syncthreads();
    float mean = (sh[0] + sh[1] + sh[2] + sh[3]) * (1.f / 128.f);
    float val = gv * rsqrtf(mean + 1e-6f) * nw[i];
    fp16 hh, ll;
    split2(val, hh, ll);
    oh[oidx] = hh;
    ol[oidx] = ll;
}

// ==================== launch ====================
extern "C" void kernel_launch(void* const* d_in, const int* in_sizes, int n_in,
                              void* d_out, int out_size) {
    const int*   ids   = (const int*)d_in[0];
    const float* tab   = (const float*)d_in[1];
    const float* Wqkvz = (const float*)d_in[2];
    const float* Wba   = (const float*)d_in[3];
    const float* cw    = (const float*)d_in[4];
    const float* cb    = (const float*)d_in[5];
    const float* A_log = (const float*)d_in[6];
    const float* dtb   = (const float*)d_in[7];
    const float* nw    = (const float*)d_in[8];
    const float* Wout  = (const float*)d_in[9];
    const float* Wlm   = (const float*)d_in[10];
    float* out = (float*)d_out;

    cudaFuncSetAttribute(gemm_mma<true>,  cudaFuncAttributeMaxDynamicSharedMemorySize, GEMM_SMEM);
    cudaFuncSetAttribute(gemm_mma<false>, cudaFuncAttributeMaxDynamicSharedMemorySize, GEMM_SMEM);

    float *x, *qkvz, *ba, *conv, *qn, *kn, *gg, *bb, *o;
    cudaGetSymbolAddress((void**)&x,    g_x);
    cudaGetSymbolAddress((void**)&qkvz, g_qkvz);
    cudaGetSymbolAddress((void**)&ba,   g_ba);
    cudaGetSymbolAddress((void**)&conv, g_conv);
    cudaGetSymbolAddress((void**)&qn,   g_qn);
    cudaGetSymbolAddress((void**)&kn,   g_kn);
    cudaGetSymbolAddress((void**)&gg,   g_g);
    cudaGetSymbolAddress((void**)&bb,   g_beta);
    cudaGetSymbolAddress((void**)&o,    g_o);

    fp16 *xh, *xl, *oh, *ol, *hh, *Wqh, *Woh, *Wlh;
    cudaGetSymbolAddress((void**)&xh, g_xh);  cudaGetSymbolAddress((void**)&xl, g_xl);
    cudaGetSymbolAddress((void**)&oh, g_oh);  cudaGetSymbolAddress((void**)&ol, g_ol);
    cudaGetSymbolAddress((void**)&hh, g_hh);
    cudaGetSymbolAddress((void**)&Wqh, g_Wqh);
    cudaGetSymbolAddress((void**)&Woh, g_Woh);
    cudaGetSymbolAddress((void**)&Wlh, g_Wlh);

    // weight transpose to fp16: W[K,N] -> [N,K]
    tsplit_kernel<<<dim3(H_ / 32, QKVZ_N / 32), dim3(32, 8)>>>(Wqkvz, Wqh, H_, QKVZ_N);
    tsplit_kernel<<<dim3(VDIM / 32, H_ / 32),   dim3(32, 8)>>>(Wout,  Woh, VDIM, H_);
    tsplit_kernel<<<dim3(H_ / 32, V_ / 32),     dim3(32, 8)>>>(Wlm,   Wlh, H_, V_);

    embed_split_kernel<<<MTOK, 256>>>(ids, tab, x, xh, xl);
    gemm_mma<true><<<dim3(MTOK / 128, QKVZ_N / 128), 256, GEMM_SMEM>>>(
        MTOK, QKVZ_N, H_, xh, xl, Wqh, qkvz, (fp16*)0, (fp16*)0);
    sgemm128<<<dim3(1, MTOK / 128), 256>>>(MTOK, 64, H_, x, Wba, ba);
    conv_silu_kernel<<<(MTOK * CDIM) / 256, 256>>>(qkvz, cw, cb, conv);
    norm_qk_kernel<<<MTOK * HK_, 128>>>(conv, qn, kn);
    gates_kernel<<<MTOK, 32>>>(ba, A_log, dtb, gg, bb);
    scan_kernel<<<B_ * HV_ * 2, 256>>>(qn, kn, conv, gg, bb, o);
    gated_norm_split<<<MTOK * HV_, 128>>>(o, qkvz, nw, oh, ol);
    // Wout: 2-term input, fp16 hi-only output (lm_head input)
    gemm_mma<true><<<dim3(MTOK / 128, H_ / 128), 256, GEMM_SMEM>>>(
        MTOK, H_, VDIM, oh, ol, Woh, (float*)0, hh, (fp16*)0);
    // lm_head: single-term
    gemm_mma<false><<<dim3(MTOK / 128, V_ / 128), 256, GEMM_SMEM>>>(
        MTOK, V_, H_, hh, (fp16*)0, Wlh, out, (fp16*)0, (fp16*)0);
}

// round 10
// speedup vs baseline: 6.0134x; 1.1219x over previous
#include <cuda_runtime.h>
#include <cuda_fp16.h>
#include <cstdint>
#include <cstddef>

#define B_    2
#define T_    1024
#define MTOK  2048
#define H_    2048
#define V_    32000
#define HK_   16
#define HV_   32
#define DK_   128
#define DV_   128
#define QKDIM 2048
#define VDIM  4096
#define CDIM  8192
#define QKVZ_N 12288

typedef __half fp16;

// ==================== scratch ====================
__device__ float g_x[MTOK * H_];
__device__ float g_qkvz[(size_t)MTOK * QKVZ_N];
__device__ float g_ba[MTOK * 64];
__device__ float g_conv[(size_t)MTOK * CDIM];
__device__ float g_qn[MTOK * QKDIM];
__device__ float g_kn[MTOK * QKDIM];
__device__ float g_g[MTOK * HV_];
__device__ float g_beta[MTOK * HV_];
__device__ float g_o[(size_t)MTOK * VDIM];

__device__ fp16 g_xh[MTOK * H_];
__device__ fp16 g_oh[(size_t)MTOK * VDIM];
__device__ fp16 g_hh[MTOK * H_];
__device__ fp16 g_Wqh[(size_t)QKVZ_N * H_];
__device__ fp16 g_Woh[(size_t)H_ * VDIM];
__device__ fp16 g_Wlh[(size_t)V_ * H_];

// ==================== helpers ====================
__device__ __forceinline__ uint32_t smem_u32(const void* p) {
    uint32_t a;
    asm("{ .reg .u64 t; cvta.to.shared.u64 t, %1; cvt.u32.u64 %0, t; }" : "=r"(a) : "l"(p));
    return a;
}
__device__ __forceinline__ void cpa16(uint32_t dst, const void* src) {
    asm volatile("cp.async.cg.shared.global [%0], [%1], 16;" :: "r"(dst), "l"(src) : "memory");
}
#define CPA_COMMIT() asm volatile("cp.async.commit_group;" ::: "memory")
#define CPA_WAIT2()  asm volatile("cp.async.wait_group 2;" ::: "memory")
#define CPA_WAIT1()  asm volatile("cp.async.wait_group 1;" ::: "memory")

__device__ __forceinline__ void ldm_x4(uint32_t* r, uint32_t addr) {
    asm volatile("ldmatrix.sync.aligned.m8n8.x4.shared.b16 {%0,%1,%2,%3}, [%4];"
                 : "=r"(r[0]), "=r"(r[1]), "=r"(r[2]), "=r"(r[3]) : "r"(addr));
}
__device__ __forceinline__ void mma16816(float* c, const uint32_t* a, const uint32_t* b) {
    asm volatile(
        "mma.sync.aligned.m16n8k16.row.col.f32.f16.f16.f32 "
        "{%0,%1,%2,%3}, {%4,%5,%6,%7}, {%8,%9}, {%0,%1,%2,%3};\n"
        : "+f"(c[0]), "+f"(c[1]), "+f"(c[2]), "+f"(c[3])
        : "r"(a[0]), "r"(a[1]), "r"(a[2]), "r"(a[3]), "r"(b[0]), "r"(b[1]));
}
#define SWZ(off) ((off) ^ (((off) >> 3) & 0x70))

// ==================== fp16 mma.sync GEMM (1 or 2 A-limb terms) ====================
#define STG_BYTES 49152
#define O_AL 16384
#define O_BH 32768
#define GEMM_SMEM (3 * STG_BYTES + 1024)

template <bool HAS_AL>
__global__ __launch_bounds__(256, 1) void gemm_mma(
    int M, int N, int K,
    const fp16* __restrict__ Ah, const fp16* __restrict__ Al,
    const fp16* __restrict__ Bh,
    float* __restrict__ Cf, fp16* __restrict__ Chi) {
    extern __shared__ char dsm_raw[];
    uint32_t dbase = (smem_u32(dsm_raw) + 1023u) & ~1023u;

    int tid = threadIdx.x;
    int lane = tid & 31, wid = tid >> 5;
    int wm = wid >> 2, wn = wid & 3;                 // warp tile 64(m) x 32(n)
    int row0 = blockIdx.x << 7;                      // m fastest: weight-stripe L2 reuse
    int col0 = blockIdx.y << 7;

    int lrow = ((lane >> 3) & 1) * 8 + (lane & 7);
    int lbyte = (lane >> 4) * 16;
    int rowA = wm * 64 + lrow;
    int rowB = wn * 32 + lrow;

    float acc[4][4][4];
#pragma unroll
    for (int i = 0; i < 4; i++)
#pragma unroll
        for (int j = 0; j < 4; j++)
#pragma unroll
            for (int r = 0; r < 4; r++) acc[i][j][r] = 0.f;

    int nk = K >> 6;

    auto load_stage = [&](int slot, int kc) {
        uint32_t stg = dbase + slot * STG_BYTES;
        int k0 = kc << 6;
#pragma unroll
        for (int i = 0; i < 4; i++) {
            int c = tid + (i << 8);
            int row = c >> 3, c8 = c & 7;
            uint32_t sw = SWZ((uint32_t)(row * 128 + c8 * 16));
            size_t ga = (size_t)(row0 + row) * K + k0 + c8 * 8;
            size_t gb = (size_t)(col0 + row) * K + k0 + c8 * 8;
            cpa16(stg + sw, Ah + ga);
            if (HAS_AL) cpa16(stg + O_AL + sw, Al + ga);
            cpa16(stg + O_BH + sw, Bh + gb);
        }
    };

    load_stage(0, 0); CPA_COMMIT();
    load_stage(1, 1); CPA_COMMIT();
    load_stage(2, 2); CPA_COMMIT();

    uint32_t fah[2][4][4], fal[2][4][4], fbh[2][4][2];

    auto loadfrag = [&](int buf, uint32_t stg, int kk) {
#pragma unroll
        for (int mi = 0; mi < 4; mi++) {
            uint32_t off = SWZ((uint32_t)((rowA + mi * 16) * 128 + kk * 32 + lbyte));
            ldm_x4(fah[buf][mi], stg + off);
            if (HAS_AL) ldm_x4(fal[buf][mi], stg + O_AL + off);
        }
#pragma unroll
        for (int nj = 0; nj < 2; nj++) {
            uint32_t off = SWZ((uint32_t)((rowB + nj * 16) * 128 + kk * 32 + lbyte));
            uint32_t rh[4];
            ldm_x4(rh, stg + O_BH + off);
            fbh[buf][nj * 2][0] = rh[0];     fbh[buf][nj * 2][1] = rh[2];
            fbh[buf][nj * 2 + 1][0] = rh[1]; fbh[buf][nj * 2 + 1][1] = rh[3];
        }
    };

    for (int kc = 0; kc < nk; kc++) {
        CPA_WAIT2();
        __syncthreads();
        uint32_t stg = dbase + (kc % 3) * STG_BYTES;
        loadfrag(0, stg, 0);
#pragma unroll
        for (int kk = 0; kk < 4; kk++) {
            int cur = kk & 1;
            if (kk < 3) loadfrag(cur ^ 1, stg, kk + 1);
#pragma unroll
            for (int mi = 0; mi < 4; mi++)
#pragma unroll
                for (int ni = 0; ni < 4; ni++) {
                    mma16816(acc[mi][ni], fah[cur][mi], fbh[cur][ni]);
                    if (HAS_AL) mma16816(acc[mi][ni], fal[cur][mi], fbh[cur][ni]);
                }
        }
        __syncthreads();
        if (kc + 3 < nk) load_stage(kc % 3, kc + 3);
        CPA_COMMIT();
    }

    // epilogue
    int g = lane >> 2, tig = lane & 3;
#pragma unroll
    for (int mi = 0; mi < 4; mi++) {
        int r = row0 + wm * 64 + mi * 16 + g;
#pragma unroll
        for (int ni = 0; ni < 4; ni++) {
            int c = col0 + wn * 32 + ni * 8 + 2 * tig;
            float a0 = acc[mi][ni][0], a1 = acc[mi][ni][1];
            float a2 = acc[mi][ni][2], a3 = acc[mi][ni][3];
            if (Cf) {
                *reinterpret_cast<float2*>(Cf + (size_t)r * N + c) = make_float2(a0, a1);
                *reinterpret_cast<float2*>(Cf + (size_t)(r + 8) * N + c) = make_float2(a2, a3);
            }
            if (Chi) {
                fp16 h0 = __float2half_rn(a0), h1 = __float2half_rn(a1);
                fp16 h2 = __float2half_rn(a2), h3 = __float2half_rn(a3);
                *reinterpret_cast<__half2*>(Chi + (size_t)r * N + c) = __halves2half2(h0, h1);
                *reinterpret_cast<__half2*>(Chi + (size_t)(r + 8) * N + c) = __halves2half2(h2, h3);
            }
        }
    }
}

// ==================== embed + fp16 ====================
__global__ void embed_split_kernel(const int* __restrict__ ids, const float* __restrict__ tab,
                                   float* __restrict__ x, fp16* __restrict__ xh) {
    int m = blockIdx.x;
    int id = ids[m];
    const float4* src = reinterpret_cast<const float4*>(tab + (size_t)id * H_);
    float4* dst = reinterpret_cast<float4*>(x + (size_t)m * H_);
    __half2* ph = reinterpret_cast<__half2*>(xh) + (size_t)m * (H_ / 2);
    for (int i = threadIdx.x; i < H_ / 4; i += blockDim.x) {
        float4 v = src[i];
        dst[i] = v;
        ph[2 * i + 0] = __halves2half2(__float2half_rn(v.x), __float2half_rn(v.y));
        ph[2 * i + 1] = __halves2half2(__float2half_rn(v.z), __float2half_rn(v.w));
    }
}

// ==================== transpose weights to fp16: W[K,N] -> Th[N,K] ====================
__global__ __launch_bounds__(256) void tsplit_kernel(const float* __restrict__ W,
                                                     fp16* __restrict__ Th,
                                                     int K, int N) {
    __shared__ float tile[32][33];
    int kb = blockIdx.x << 5, nb = blockIdx.y << 5;
    int tx = threadIdx.x, ty = threadIdx.y;  // (32, 8)
#pragma unroll
    for (int j = 0; j < 4; j++)
        tile[ty + j * 8][tx] = W[(size_t)(kb + ty + j * 8) * N + nb + tx];
    __syncthreads();
#pragma unroll
    for (int j = 0; j < 4; j++) {
        float v = tile[tx][ty + j * 8];
        Th[(size_t)(nb + ty + j * 8) * K + kb + tx] = __float2half_rn(v);
    }
}

// ==================== small fp32 SGEMM (ba: N=64) ====================
__global__ __launch_bounds__(256) void sgemm128(int M, int N, int K,
                                                const float* __restrict__ A,
                                                const float* __restrict__ Bm,
                                                float* __restrict__ C) {
    __shared__ float As[8][128];
    __shared__ float Bs[8][128];
    int tid = threadIdx.x;
    int cRow = blockIdx.y << 7;
    int cCol = blockIdx.x << 7;
    int aRow = tid >> 1, aCol = (tid & 1) << 2;
    int bRow = tid >> 5, bCol = (tid & 31) << 2;
    int tr = (tid >> 4) << 3, tc = (tid & 15) << 3;
    float acc[8][8];
#pragma unroll
    for (int i = 0; i < 8; i++)
#pragma unroll
        for (int j = 0; j < 8; j++) acc[i][j] = 0.f;
    const float* aptr = A + (size_t)(cRow + aRow) * K + aCol;
    bool bok = (cCol + bCol) < N;
    const float* bptr = Bm + (size_t)bRow * N + cCol + bCol;
    for (int k0 = 0; k0 < K; k0 += 8) {
        float4 av = *reinterpret_cast<const float4*>(aptr + k0);
        As[aCol + 0][aRow] = av.x; As[aCol + 1][aRow] = av.y;
        As[aCol + 2][aRow] = av.z; As[aCol + 3][aRow] = av.w;
        float4 bv = make_float4(0.f, 0.f, 0.f, 0.f);
        if (bok) bv = *reinterpret_cast<const float4*>(bptr + (size_t)k0 * N);
        *reinterpret_cast<float4*>(&Bs[bRow][bCol]) = bv;
        __syncthreads();
#pragma unroll
        for (int kk = 0; kk < 8; kk++) {
            float4 a0 = *reinterpret_cast<const float4*>(&As[kk][tr]);
            float4 a1 = *reinterpret_cast<const float4*>(&As[kk][tr + 4]);
            float4 b0 = *reinterpret_cast<const float4*>(&Bs[kk][tc]);
            float4 b1 = *reinterpret_cast<const float4*>(&Bs[kk][tc + 4]);
            float ar[8] = {a0.x, a0.y, a0.z, a0.w, a1.x, a1.y, a1.z, a1.w};
            float br[8] = {b0.x, b0.y, b0.z, b0.w, b1.x, b1.y, b1.z, b1.w};
#pragma unroll
            for (int i = 0; i < 8; i++)
#pragma unroll
                for (int j = 0; j < 8; j++) acc[i][j] += ar[i] * br[j];
        }
        __syncthreads();
    }
#pragma unroll
    for (int i = 0; i < 8; i++) {
        size_t r = (size_t)(cRow + tr + i);
#pragma unroll
        for (int j = 0; j < 8; j += 4) {
            int c = cCol + tc + j;
            if (c < N)
                *reinterpret_cast<float4*>(C + r * N + c) =
                    make_float4(acc[i][j], acc[i][j + 1], acc[i][j + 2], acc[i][j + 3]);
        }
    }
}

// ==================== conv + silu ====================
__global__ void conv_silu_kernel(const float* __restrict__ qkvz, const float* __restrict__ cw,
                                 const float* __restrict__ cb, float* __restrict__ out) {
    int idx = blockIdx.x * blockDim.x + threadIdx.x;
    int c = idx & (CDIM - 1);
    int m = idx >> 13;
    int t = m & (T_ - 1);
    const float* w = cw + c * 4;
    float s = cb[c];
#pragma unroll
    for (int j = 0; j < 4; j++) {
        int tt = t - 3 + j;
        if (tt >= 0) s += w[j] * qkvz[(size_t)(m - 3 + j) * QKVZ_N + c];
    }
    out[(size_t)m * CDIM + c] = s / (1.f + expf(-s));
}

// ==================== l2norm q/k ====================
__global__ __launch_bounds__(128) void norm_qk_kernel(const float* __restrict__ conv,
                                                      float* __restrict__ qn,
                                                      float* __restrict__ kn) {
    int m = blockIdx.x >> 4;
    int hh = blockIdx.x & 15;
    int i = threadIdx.x;
    const float* qr = conv + (size_t)m * CDIM + hh * DK_;
    const float* kr = conv + (size_t)m * CDIM + QKDIM + hh * DK_;
    float qv = qr[i], kv = kr[i];
    float q2 = qv * qv, k2 = kv * kv;
#pragma unroll
    for (int off = 16; off; off >>= 1) {
        q2 += __shfl_xor_sync(0xffffffffu, q2, off);
        k2 += __shfl_xor_sync(0xffffffffu, k2, off);
    }
    __shared__ float shq[4], shk[4];
    if ((i & 31) == 0) { shq[i >> 5] = q2; shk[i >> 5] = k2; }
    __syncthreads();
    float sq = shq[0] + shq[1] + shq[2] + shq[3];
    float sk = shk[0] + shk[1] + shk[2] + shk[3];
    qn[(size_t)m * QKDIM + hh * DK_ + i] = qv * rsqrtf(sq + 1e-6f) * 0.08838834764831845f;
    kn[(size_t)m * QKDIM + hh * DK_ + i] = kv * rsqrtf(sk + 1e-6f);
}

// ==================== gates ====================
__global__ void gates_kernel(const float* __restrict__ ba, const float* __restrict__ A_log,
                             const float* __restrict__ dtb, float* __restrict__ g,
                             float* __restrict__ beta) {
    int m = blockIdx.x;
    int h = threadIdx.x;
    float bv = ba[m * 64 + h];
    float av = ba[m * 64 + 32 + h];
    beta[m * HV_ + h] = 1.f / (1.f + expf(-bv));
    float x = av + dtb[h];
    float sp = (x > 20.f) ? x : log1pf(expf(x));
    g[m * HV_ + h] = -expf(A_log[h]) * sp;
}

// ==================== scan (cp.async prefetch pipeline) ====================
__global__ __launch_bounds__(256) void scan_kernel(const float* __restrict__ qn,
                                                   const float* __restrict__ kn,
                                                   const float* __restrict__ conv,
                                                   const float* __restrict__ gg,
                                                   const float* __restrict__ bb,
                                                   float* __restrict__ o) {
    int bid = blockIdx.x;
    int split = bid & 1;
    int h = (bid >> 1) & 31;
    int b = bid >> 6;
    int kh = h >> 1;
    int v0 = split * 64;
    int tid = threadIdx.x;
    int vloc = tid >> 2;
    int kseg = tid & 3;
    int k0 = kseg * 32;

    __shared__ float sk[3][128], sq[3][128];

    float S[32];
#pragma unroll
    for (int i = 0; i < 32; i++) S[i] = 0.f;

    const float* qrow = qn + (size_t)(b * T_) * QKDIM + kh * DK_;
    const float* krow = kn + (size_t)(b * T_) * QKDIM + kh * DK_;
    const float* vrow = conv + (size_t)(b * T_) * CDIM + 2 * QKDIM + h * DV_ + v0 + vloc;
    const float* grow = gg + (b * T_) * HV_ + h;
    const float* brow = bb + (b * T_) * HV_ + h;
    float* orow = o + (size_t)(b * T_) * VDIM + h * DV_ + v0 + vloc;

    auto prefetch = [&](int t) {
        if (t < T_) {
            int buf = t % 3;
            if (tid < 32)
                cpa16(smem_u32(&sk[buf][tid * 4]), krow + (size_t)t * QKDIM + tid * 4);
            else if (tid < 64)
                cpa16(smem_u32(&sq[buf][(tid - 32) * 4]), qrow + (size_t)t * QKDIM + (tid - 32) * 4);
        }
        CPA_COMMIT();
    };

    prefetch(0);
    float vt0 = vrow[0], gt0 = grow[0], bt0 = brow[0];
    float vt1 = vrow[CDIM], gt1 = grow[HV_], bt1 = brow[HV_];

    for (int t = 0; t < T_; t++) {
        prefetch(t + 1);
        float vt2 = 0.f, gt2 = 0.f, bt2 = 0.f;
        if (t + 2 < T_) {
            vt2 = vrow[(size_t)(t + 2) * CDIM];
            gt2 = grow[(size_t)(t + 2) * HV_];
            bt2 = brow[(size_t)(t + 2) * HV_];
        }
        CPA_WAIT1();
        __syncthreads();
        int buf = t % 3;
        float decay = expf(gt0);
        float pkv = 0.f;
#pragma unroll
        for (int i = 0; i < 32; i++) {
            float s = S[i] * decay;
            S[i] = s;
            pkv += sk[buf][k0 + i] * s;
        }
        pkv += __shfl_xor_sync(0xffffffffu, pkv, 1);
        pkv += __shfl_xor_sync(0xffffffffu, pkv, 2);
        float delta = (vt0 - pkv) * bt0;
        float po = 0.f;
#pragma unroll
        for (int i = 0; i < 32; i++) {
            float s = S[i] + sk[buf][k0 + i] * delta;
            S[i] = s;
            po += sq[buf][k0 + i] * s;
        }
        po += __shfl_xor_sync(0xffffffffu, po, 1);
        po += __shfl_xor_sync(0xffffffffu, po, 2);
        if (kseg == 0) orow[(size_t)t * VDIM] = po;
        vt0 = vt1; gt0 = gt1; bt0 = bt1;
        vt1 = vt2; gt1 = gt2; bt1 = bt2;
    }
}

// ==================== gated RMSNorm -> fp16 ====================
__global__ __launch_bounds__(128) void gated_norm_split(const float* __restrict__ o,
                                                        const float* __restrict__ qkvz,
                                                        const float* __restrict__ nw,
                                                        fp16* __restrict__ oh) {
    int m = blockIdx.x >> 5;
    int h = blockIdx.x & 31;
    int i = threadIdx.x;
    size_t oidx = (size_t)m * VDIM + h * DV_ + i;
    float ov = o[oidx];
    float zv = qkvz[(size_t)m * QKVZ_N + 2 * QKDIM + VDIM + h * DV_ + i];
    float gv = ov * (zv / (1.f + expf(-zv)));
    float s2 = gv * gv;
#pragma unroll
    for (int off = 16; off; off >>= 1) s2 += __shfl_xor_sync(0xffffffffu, s2, off);
    __shared__ float sh[4];
    if ((i & 31) == 0) sh[i >> 5] = s2;
    __syncthreads();
    float mean = (sh[0] + sh[1] + sh[2] + sh[3]) * (1.f / 128.f);
    float val = gv * rsqrtf(mean + 1e-6f) * nw[i];
    oh[oidx] = __float2half_rn(val);
}

// ==================== launch ====================
extern "C" void kernel_launch(void* const* d_in, const int* in_sizes, int n_in,
                              void* d_out, int out_size) {
    const int*   ids   = (const int*)d_in[0];
    const float* tab   = (const float*)d_in[1];
    const float* Wqkvz = (const float*)d_in[2];
    const float* Wba   = (const float*)d_in[3];
    const float* cw    = (const float*)d_in[4];
    const float* cb    = (const float*)d_in[5];
    const float* A_log = (const float*)d_in[6];
    const float* dtb   = (const float*)d_in[7];
    const float* nw    = (const float*)d_in[8];
    const float* Wout  = (const float*)d_in[9];
    const float* Wlm   = (const float*)d_in[10];
    float* out = (float*)d_out;

    cudaFuncSetAttribute(gemm_mma<false>, cudaFuncAttributeMaxDynamicSharedMemorySize, GEMM_SMEM);

    float *x, *qkvz, *ba, *conv, *qn, *kn, *gg, *bb, *o;
    cudaGetSymbolAddress((void**)&x,    g_x);
    cudaGetSymbolAddress((void**)&qkvz, g_qkvz);
    cudaGetSymbolAddress((void**)&ba,   g_ba);
    cudaGetSymbolAddress((void**)&conv, g_conv);
    cudaGetSymbolAddress((void**)&qn,   g_qn);
    cudaGetSymbolAddress((void**)&kn,   g_kn);
    cudaGetSymbolAddress((void**)&gg,   g_g);
    cudaGetSymbolAddress((void**)&bb,   g_beta);
    cudaGetSymbolAddress((void**)&o,    g_o);

    fp16 *xh, *oh, *hh, *Wqh, *Woh, *Wlh;
    cudaGetSymbolAddress((void**)&xh, g_xh);
    cudaGetSymbolAddress((void**)&oh, g_oh);
    cudaGetSymbolAddress((void**)&hh, g_hh);
    cudaGetSymbolAddress((void**)&Wqh, g_Wqh);
    cudaGetSymbolAddress((void**)&Woh, g_Woh);
    cudaGetSymbolAddress((void**)&Wlh, g_Wlh);

    // weight transpose to fp16: W[K,N] -> [N,K]
    tsplit_kernel<<<dim3(H_ / 32, QKVZ_N / 32), dim3(32, 8)>>>(Wqkvz, Wqh, H_, QKVZ_N);
    tsplit_kernel<<<dim3(VDIM / 32, H_ / 32),   dim3(32, 8)>>>(Wout,  Woh, VDIM, H_);
    tsplit_kernel<<<dim3(H_ / 32, V_ / 32),     dim3(32, 8)>>>(Wlm,   Wlh, H_, V_);

    embed_split_kernel<<<MTOK, 256>>>(ids, tab, x, xh);
    gemm_mma<false><<<dim3(MTOK / 128, QKVZ_N / 128), 256, GEMM_SMEM>>>(
        MTOK, QKVZ_N, H_, xh, (fp16*)0, Wqh, qkvz, (fp16*)0);
    sgemm128<<<dim3(1, MTOK / 128), 256>>>(MTOK, 64, H_, x, Wba, ba);
    conv_silu_kernel<<<(MTOK * CDIM) / 256, 256>>>(qkvz, cw, cb, conv);
    norm_qk_kernel<<<MTOK * HK_, 128>>>(conv, qn, kn);
    gates_kernel<<<MTOK, 32>>>(ba, A_log, dtb, gg, bb);
    scan_kernel<<<B_ * HV_ * 2, 256>>>(qn, kn, conv, gg, bb, o);
    gated_norm_split<<<MTOK * HV_, 128>>>(o, qkvz, nw, oh);
    gemm_mma<false><<<dim3(MTOK / 128, H_ / 128), 256, GEMM_SMEM>>>(
        MTOK, H_, VDIM, oh, (fp16*)0, Woh, (float*)0, hh);
    gemm_mma<false><<<dim3(MTOK / 128, V_ / 128), 256, GEMM_SMEM>>>(
        MTOK, V_, H_, hh, (fp16*)0, Wlh, out, (fp16*)0);
}

// round 12
// speedup vs baseline: 6.7863x; 1.1285x over previous
#include <cuda_runtime.h>
#include <cuda_fp16.h>
#include <cstdint>
#include <cstddef>

#define B_    2
#define T_    1024
#define MTOK  2048
#define H_    2048
#define V_    32000
#define HK_   16
#define HV_   32
#define DK_   128
#define DV_   128
#define QKDIM 2048
#define VDIM  4096
#define CDIM  8192
#define QW    12416   // combined qkvz+ba output width (12288 qkvz + 64 ba + 64 pad)

typedef __half fp16;

// ==================== scratch ====================
__device__ float g_qkvz[(size_t)MTOK * QW];      // qkvz (cols 0..12287) + ba (12288..12351)
__device__ float g_conv[(size_t)MTOK * CDIM];
__device__ float g_qn[MTOK * QKDIM];
__device__ float g_kn[MTOK * QKDIM];
__device__ float g_g[MTOK * HV_];
__device__ float g_beta[MTOK * HV_];
__device__ float g_o[(size_t)MTOK * VDIM];

__device__ fp16 g_xh[MTOK * H_];
__device__ fp16 g_oh[(size_t)MTOK * VDIM];
__device__ fp16 g_hh[MTOK * H_];
__device__ fp16 g_Wqh[(size_t)QW * H_];          // rows 0..12287 Wqkvz^T, 12288..12351 Wba^T, rest zero-init
__device__ fp16 g_Woh[(size_t)H_ * VDIM];
__device__ fp16 g_Wlh[(size_t)V_ * H_];

// ==================== helpers ====================
__device__ __forceinline__ uint32_t smem_u32(const void* p) {
    uint32_t a;
    asm("{ .reg .u64 t; cvta.to.shared.u64 t, %1; cvt.u32.u64 %0, t; }" : "=r"(a) : "l"(p));
    return a;
}
__device__ __forceinline__ void cpa16(uint32_t dst, const void* src) {
    asm volatile("cp.async.cg.shared.global [%0], [%1], 16;" :: "r"(dst), "l"(src) : "memory");
}
#define CPA_COMMIT() asm volatile("cp.async.commit_group;" ::: "memory")
#define CPA_WAIT2()  asm volatile("cp.async.wait_group 2;" ::: "memory")
#define CPA_WAIT1()  asm volatile("cp.async.wait_group 1;" ::: "memory")

__device__ __forceinline__ void ldm_x4(uint32_t* r, uint32_t addr) {
    asm volatile("ldmatrix.sync.aligned.m8n8.x4.shared.b16 {%0,%1,%2,%3}, [%4];"
                 : "=r"(r[0]), "=r"(r[1]), "=r"(r[2]), "=r"(r[3]) : "r"(addr));
}
__device__ __forceinline__ void mma16816(float* c, const uint32_t* a, const uint32_t* b) {
    asm volatile(
        "mma.sync.aligned.m16n8k16.row.col.f32.f16.f16.f32 "
        "{%0,%1,%2,%3}, {%4,%5,%6,%7}, {%8,%9}, {%0,%1,%2,%3};\n"
        : "+f"(c[0]), "+f"(c[1]), "+f"(c[2]), "+f"(c[3])
        : "r"(a[0]), "r"(a[1]), "r"(a[2]), "r"(a[3]), "r"(b[0]), "r"(b[1]));
}
#define SWZ(off) ((off) ^ (((off) >> 3) & 0x70))

// ==================== fp16 mma.sync GEMM ====================
#define STG_BYTES 49152
#define O_BH 32768
#define GEMM_SMEM (3 * STG_BYTES + 1024)

__global__ __launch_bounds__(256, 1) void gemm_mma(
    int M, int N, int K,
    const fp16* __restrict__ Ah,
    const fp16* __restrict__ Bh,
    float* __restrict__ Cf, fp16* __restrict__ Chi) {
    extern __shared__ char dsm_raw[];
    uint32_t dbase = (smem_u32(dsm_raw) + 1023u) & ~1023u;

    int tid = threadIdx.x;
    int lane = tid & 31, wid = tid >> 5;
    int wm = wid >> 2, wn = wid & 3;                 // warp tile 64(m) x 32(n)
    int row0 = blockIdx.x << 7;                      // m fastest: weight-stripe L2 reuse
    int col0 = blockIdx.y << 7;

    int lrow = ((lane >> 3) & 1) * 8 + (lane & 7);
    int lbyte = (lane >> 4) * 16;
    int rowA = wm * 64 + lrow;
    int rowB = wn * 32 + lrow;

    float acc[4][4][4];
#pragma unroll
    for (int i = 0; i < 4; i++)
#pragma unroll
        for (int j = 0; j < 4; j++)
#pragma unroll
            for (int r = 0; r < 4; r++) acc[i][j][r] = 0.f;

    int nk = K >> 6;

    auto load_stage = [&](int slot, int kc) {
        uint32_t stg = dbase + slot * STG_BYTES;
        int k0 = kc << 6;
#pragma unroll
        for (int i = 0; i < 4; i++) {
            int c = tid + (i << 8);
            int row = c >> 3, c8 = c & 7;
            uint32_t sw = SWZ((uint32_t)(row * 128 + c8 * 16));
            size_t ga = (size_t)(row0 + row) * K + k0 + c8 * 8;
            size_t gb = (size_t)(col0 + row) * K + k0 + c8 * 8;
            cpa16(stg + sw, Ah + ga);
            cpa16(stg + O_BH + sw, Bh + gb);
        }
    };

    load_stage(0, 0); CPA_COMMIT();
    load_stage(1, 1); CPA_COMMIT();
    load_stage(2, 2); CPA_COMMIT();

    uint32_t fah[2][4][4], fbh[2][4][2];

    auto loadfrag = [&](int buf, uint32_t stg, int kk) {
#pragma unroll
        for (int mi = 0; mi < 4; mi++) {
            uint32_t off = SWZ((uint32_t)((rowA + mi * 16) * 128 + kk * 32 + lbyte));
            ldm_x4(fah[buf][mi], stg + off);
        }
#pragma unroll
        for (int nj = 0; nj < 2; nj++) {
            uint32_t off = SWZ((uint32_t)((rowB + nj * 16) * 128 + kk * 32 + lbyte));
            uint32_t rh[4];
            ldm_x4(rh, stg + O_BH + off);
            fbh[buf][nj * 2][0] = rh[0];     fbh[buf][nj * 2][1] = rh[2];
            fbh[buf][nj * 2 + 1][0] = rh[1]; fbh[buf][nj * 2 + 1][1] = rh[3];
        }
    };

    for (int kc = 0; kc < nk; kc++) {
        CPA_WAIT2();
        __syncthreads();
        uint32_t stg = dbase + (kc % 3) * STG_BYTES;
        loadfrag(0, stg, 0);
#pragma unroll
        for (int kk = 0; kk < 4; kk++) {
            int cur = kk & 1;
            if (kk < 3) loadfrag(cur ^ 1, stg, kk + 1);
#pragma unroll
            for (int mi = 0; mi < 4; mi++)
#pragma unroll
                for (int ni = 0; ni < 4; ni++)
                    mma16816(acc[mi][ni], fah[cur][mi], fbh[cur][ni]);
        }
        __syncthreads();
        if (kc + 3 < nk) load_stage(kc % 3, kc + 3);
        CPA_COMMIT();
    }

    // epilogue
    int g = lane >> 2, tig = lane & 3;
#pragma unroll
    for (int mi = 0; mi < 4; mi++) {
        int r = row0 + wm * 64 + mi * 16 + g;
#pragma unroll
        for (int ni = 0; ni < 4; ni++) {
            int c = col0 + wn * 32 + ni * 8 + 2 * tig;
            float a0 = acc[mi][ni][0], a1 = acc[mi][ni][1];
            float a2 = acc[mi][ni][2], a3 = acc[mi][ni][3];
            if (Cf) {
                *reinterpret_cast<float2*>(Cf + (size_t)r * N + c) = make_float2(a0, a1);
                *reinterpret_cast<float2*>(Cf + (size_t)(r + 8) * N + c) = make_float2(a2, a3);
            }
            if (Chi) {
                *reinterpret_cast<__half2*>(Chi + (size_t)r * N + c) =
                    __halves2half2(__float2half_rn(a0), __float2half_rn(a1));
                *reinterpret_cast<__half2*>(Chi + (size_t)(r + 8) * N + c) =
                    __halves2half2(__float2half_rn(a2), __float2half_rn(a3));
            }
        }
    }
}

// ==================== embed -> fp16 only ====================
__global__ void embed_split_kernel(const int* __restrict__ ids, const float* __restrict__ tab,
                                   fp16* __restrict__ xh) {
    int m = blockIdx.x;
    int id = ids[m];
    const float4* src = reinterpret_cast<const float4*>(tab + (size_t)id * H_);
    __half2* ph = reinterpret_cast<__half2*>(xh) + (size_t)m * (H_ / 2);
    for (int i = threadIdx.x; i < H_ / 4; i += blockDim.x) {
        float4 v = src[i];
        ph[2 * i + 0] = __halves2half2(__float2half_rn(v.x), __float2half_rn(v.y));
        ph[2 * i + 1] = __halves2half2(__float2half_rn(v.z), __float2half_rn(v.w));
    }
}

// ==================== transpose weights to fp16: W[K,N] -> Th[N,K], half2 writes ====================
__global__ __launch_bounds__(256) void tsplit_kernel(const float* __restrict__ W,
                                                     fp16* __restrict__ Th,
                                                     int K, int N) {
    __shared__ float tile[32][33];
    int kb = blockIdx.x << 5, nb = blockIdx.y << 5;
    int tx = threadIdx.x, ty = threadIdx.y;  // (32, 8)
#pragma unroll
    for (int j = 0; j < 4; j++)
        tile[ty + j * 8][tx] = W[(size_t)(kb + ty + j * 8) * N + nb + tx];
    __syncthreads();
    int tid = ty * 32 + tx;
    int n_loc = tid >> 4;          // 0..15
    int k2 = (tid & 15) * 2;       // 0,2,..,30
#pragma unroll
    for (int j = 0; j < 2; j++) {
        int n = n_loc + j * 16;
        __half2 v = __halves2half2(__float2half_rn(tile[k2][n]),
                                   __float2half_rn(tile[k2 + 1][n]));
        *reinterpret_cast<__half2*>(Th + (size_t)(nb + n) * K + kb + k2) = v;
    }
}

// ==================== conv + silu (float4, 4 channels/thread) ====================
__global__ void conv_silu_kernel(const float* __restrict__ qkvz, const float* __restrict__ cw,
                                 const float* __restrict__ cb, float* __restrict__ out) {
    int idx = blockIdx.x * blockDim.x + threadIdx.x;   // over MTOK*CDIM/4
    int c4 = (idx << 2) & (CDIM - 1);
    int m = idx >> 11;                                 // CDIM/4 = 2048
    int t = m & (T_ - 1);
    const float4* wv = reinterpret_cast<const float4*>(cw + c4 * 4);
    float4 w0 = wv[0], w1 = wv[1], w2 = wv[2], w3 = wv[3];   // taps for channels c4..c4+3
    float4 s = *reinterpret_cast<const float4*>(cb + c4);
    float wtap[4][4] = {{w0.x, w0.y, w0.z, w0.w}, {w1.x, w1.y, w1.z, w1.w},
                        {w2.x, w2.y, w2.z, w2.w}, {w3.x, w3.y, w3.z, w3.w}};
#pragma unroll
    for (int j = 0; j < 4; j++) {
        int tt = t - 3 + j;
        if (tt >= 0) {
            float4 v = *reinterpret_cast<const float4*>(qkvz + (size_t)(m - 3 + j) * QW + c4);
            s.x += wtap[0][j] * v.x;
            s.y += wtap[1][j] * v.y;
            s.z += wtap[2][j] * v.z;
            s.w += wtap[3][j] * v.w;
        }
    }
    s.x = s.x / (1.f + expf(-s.x));
    s.y = s.y / (1.f + expf(-s.y));
    s.z = s.z / (1.f + expf(-s.z));
    s.w = s.w / (1.f + expf(-s.w));
    *reinterpret_cast<float4*>(out + (size_t)m * CDIM + c4) = s;
}

// ==================== l2norm q/k ====================
__global__ __launch_bounds__(128) void norm_qk_kernel(const float* __restrict__ conv,
                                                      float* __restrict__ qn,
                                                      float* __restrict__ kn) {
    int m = blockIdx.x >> 4;
    int hh = blockIdx.x & 15;
    int i = threadIdx.x;
    const float* qr = conv + (size_t)m * CDIM + hh * DK_;
    const float* kr = conv + (size_t)m * CDIM + QKDIM + hh * DK_;
    float qv = qr[i], kv = kr[i];
    float q2 = qv * qv, k2 = kv * kv;
#pragma unroll
    for (int off = 16; off; off >>= 1) {
        q2 += __shfl_xor_sync(0xffffffffu, q2, off);
        k2 += __shfl_xor_sync(0xffffffffu, k2, off);
    }
    __shared__ float shq[4], shk[4];
    if ((i & 31) == 0) { shq[i >> 5] = q2; shk[i >> 5] = k2; }
    __syncthreads();
    float sq = shq[0] + shq[1] + shq[2] + shq[3];
    float sk = shk[0] + shk[1] + shk[2] + shk[3];
    qn[(size_t)m * QKDIM + hh * DK_ + i] = qv * rsqrtf(sq + 1e-6f) * 0.08838834764831845f;
    kn[(size_t)m * QKDIM + hh * DK_ + i] = kv * rsqrtf(sk + 1e-6f);
}

// ==================== gates (reads b,a from combined GEMM output) ====================
__global__ void gates_kernel(const float* __restrict__ qkvz, const float* __restrict__ A_log,
                             const float* __restrict__ dtb, float* __restrict__ g,
                             float* __restrict__ beta) {
    int m = blockIdx.x;
    int h = threadIdx.x;
    float bv = qkvz[(size_t)m * QW + 12288 + h];
    float av = qkvz[(size_t)m * QW + 12320 + h];
    beta[m * HV_ + h] = 1.f / (1.f + expf(-bv));
    float x = av + dtb[h];
    float sp = (x > 20.f) ? x : log1pf(expf(x));
    g[m * HV_ + h] = -expf(A_log[h]) * sp;
}

// ==================== scan (cp.async prefetch + split accumulators) ====================
__global__ __launch_bounds__(256) void scan_kernel(const float* __restrict__ qn,
                                                   const float* __restrict__ kn,
                                                   const float* __restrict__ conv,
                                                   const float* __restrict__ gg,
                                                   const float* __restrict__ bb,
                                                   float* __restrict__ o) {
    int bid = blockIdx.x;
    int split = bid & 1;
    int h = (bid >> 1) & 31;
    int b = bid >> 6;
    int kh = h >> 1;
    int v0 = split * 64;
    int tid = threadIdx.x;
    int vloc = tid >> 2;
    int kseg = tid & 3;
    int k0 = kseg * 32;

    __shared__ float sk[3][128], sq[3][128];

    float S[32];
#pragma unroll
    for (int i = 0; i < 32; i++) S[i] = 0.f;

    const float* qrow = qn + (size_t)(b * T_) * QKDIM + kh * DK_;
    const float* krow = kn + (size_t)(b * T_) * QKDIM + kh * DK_;
    const float* vrow = conv + (size_t)(b * T_) * CDIM + 2 * QKDIM + h * DV_ + v0 + vloc;
    const float* grow = gg + (b * T_) * HV_ + h;
    const float* brow = bb + (b * T_) * HV_ + h;
    float* orow = o + (size_t)(b * T_) * VDIM + h * DV_ + v0 + vloc;

    auto prefetch = [&](int t) {
        if (t < T_) {
            int buf = t % 3;
            if (tid < 32)
                cpa16(smem_u32(&sk[buf][tid * 4]), krow + (size_t)t * QKDIM + tid * 4);
            else if (tid < 64)
                cpa16(smem_u32(&sq[buf][(tid - 32) * 4]), qrow + (size_t)t * QKDIM + (tid - 32) * 4);
        }
        CPA_COMMIT();
    };

    prefetch(0);
    float vt0 = vrow[0], gt0 = grow[0], bt0 = brow[0];
    float vt1 = vrow[CDIM], gt1 = grow[HV_], bt1 = brow[HV_];

    for (int t = 0; t < T_; t++) {
        prefetch(t + 1);
        float vt2 = 0.f, gt2 = 0.f, bt2 = 0.f;
        if (t + 2 < T_) {
            vt2 = vrow[(size_t)(t + 2) * CDIM];
            gt2 = grow[(size_t)(t + 2) * HV_];
            bt2 = brow[(size_t)(t + 2) * HV_];
        }
        CPA_WAIT1();
        __syncthreads();
        int buf = t % 3;
        float decay = expf(gt0);
        float p0 = 0.f, p1 = 0.f, p2 = 0.f, p3 = 0.f;
#pragma unroll
        for (int i = 0; i < 32; i += 4) {
            float s0 = S[i + 0] * decay; S[i + 0] = s0; p0 += sk[buf][k0 + i + 0] * s0;
            float s1 = S[i + 1] * decay; S[i + 1] = s1; p1 += sk[buf][k0 + i + 1] * s1;
            float s2 = S[i + 2] * decay; S[i + 2] = s2; p2 += sk[buf][k0 + i + 2] * s2;
            float s3 = S[i + 3] * decay; S[i + 3] = s3; p3 += sk[buf][k0 + i + 3] * s3;
        }
        float pkv = (p0 + p1) + (p2 + p3);
        pkv += __shfl_xor_sync(0xffffffffu, pkv, 1);
        pkv += __shfl_xor_sync(0xffffffffu, pkv, 2);
        float delta = (vt0 - pkv) * bt0;
        float q0 = 0.f, q1 = 0.f, q2 = 0.f, q3 = 0.f;
#pragma unroll
        for (int i = 0; i < 32; i += 4) {
            float s0 = S[i + 0] + sk[buf][k0 + i + 0] * delta; S[i + 0] = s0; q0 += sq[buf][k0 + i + 0] * s0;
            float s1 = S[i + 1] + sk[buf][k0 + i + 1] * delta; S[i + 1] = s1; q1 += sq[buf][k0 + i + 1] * s1;
            float s2 = S[i + 2] + sk[buf][k0 + i + 2] * delta; S[i + 2] = s2; q2 += sq[buf][k0 + i + 2] * s2;
            float s3 = S[i + 3] + sk[buf][k0 + i + 3] * delta; S[i + 3] = s3; q3 += sq[buf][k0 + i + 3] * s3;
        }
        float po = (q0 + q1) + (q2 + q3);
        po += __shfl_xor_sync(0xffffffffu, po, 1);
        po += __shfl_xor_sync(0xffffffffu, po, 2);
        if (kseg == 0) orow[(size_t)t * VDIM] = po;
        vt0 = vt1; gt0 = gt1; bt0 = bt1;
        vt1 = vt2; gt1 = gt2; bt1 = bt2;
    }
}

// ==================== gated RMSNorm -> fp16 ====================
__global__ __launch_bounds__(128) void gated_norm_split(const float* __restrict__ o,
                                                        const float* __restrict__ qkvz,
                                                        const float* __restrict__ nw,
                                                        fp16* __restrict__ oh) {
    int m = blockIdx.x >> 5;
    int h = blockIdx.x & 31;
    int i = threadIdx.x;
    size_t oidx = (size_t)m * VDIM + h * DV_ + i;
    float ov = o[oidx];
    float zv = qkvz[(size_t)m * QW + 2 * QKDIM + VDIM + h * DV_ + i];
    float gv = ov * (zv / (1.f + expf(-zv)));
    float s2 = gv * gv;
#pragma unroll
    for (int off = 16; off; off >>= 1) s2 += __shfl_xor_sync(0xffffffffu, s2, off);
    __shared__ float sh[4];
    if ((i & 31) == 0) sh[i >> 5] = s2;
    __syncthreads();
    float mean = (sh[0] + sh[1] + sh[2] + sh[3]) * (1.f / 128.f);
    float val = gv * rsqrtf(mean + 1e-6f) * nw[i];
    oh[oidx] = __float2half_rn(val);
}

// ==================== launch ====================
extern "C" void kernel_launch(void* const* d_in, const int* in_sizes, int n_in,
                              void* d_out, int out_size) {
    const int*   ids   = (const int*)d_in[0];
    const float* tab   = (const float*)d_in[1];
    const float* Wqkvz = (const float*)d_in[2];
    const float* Wba   = (const float*)d_in[3];
    const float* cw    = (const float*)d_in[4];
    const float* cb    = (const float*)d_in[5];
    const float* A_log = (const float*)d_in[6];
    const float* dtb   = (const float*)d_in[7];
    const float* nw    = (const float*)d_in[8];
    const float* Wout  = (const float*)d_in[9];
    const float* Wlm   = (const float*)d_in[10];
    float* out = (float*)d_out;

    cudaFuncSetAttribute(gemm_mma, cudaFuncAttributeMaxDynamicSharedMemorySize, GEMM_SMEM);

    float *qkvz, *conv, *qn, *kn, *gg, *bb, *o;
    cudaGetSymbolAddress((void**)&qkvz, g_qkvz);
    cudaGetSymbolAddress((void**)&conv, g_conv);
    cudaGetSymbolAddress((void**)&qn,   g_qn);
    cudaGetSymbolAddress((void**)&kn,   g_kn);
    cudaGetSymbolAddress((void**)&gg,   g_g);
    cudaGetSymbolAddress((void**)&bb,   g_beta);
    cudaGetSymbolAddress((void**)&o,    g_o);

    fp16 *xh, *oh, *hh, *Wqh, *Woh, *Wlh;
    cudaGetSymbolAddress((void**)&xh, g_xh);
    cudaGetSymbolAddress((void**)&oh, g_oh);
    cudaGetSymbolAddress((void**)&hh, g_hh);
    cudaGetSymbolAddress((void**)&Wqh, g_Wqh);
    cudaGetSymbolAddress((void**)&Woh, g_Woh);
    cudaGetSymbolAddress((void**)&Wlh, g_Wlh);

    // weight transpose to fp16: W[K,N] -> [N,K]
    tsplit_kernel<<<dim3(H_ / 32, 12288 / 32), dim3(32, 8)>>>(Wqkvz, Wqh, H_, 12288);
    // Wba[H,64] -> rows 12288..12351 of Wqh (pad rows 12352..12415 stay zero-init; their
    // output columns are never read)
    tsplit_kernel<<<dim3(H_ / 32, 64 / 32), dim3(32, 8)>>>(Wba, Wqh + (size_t)12288 * H_, H_, 64);
    tsplit_kernel<<<dim3(VDIM / 32, H_ / 32), dim3(32, 8)>>>(Wout, Woh, VDIM, H_);
    tsplit_kernel<<<dim3(H_ / 32, V_ / 32),   dim3(32, 8)>>>(Wlm,  Wlh, H_, V_);

    embed_split_kernel<<<MTOK, 256>>>(ids, tab, xh);
    gemm_mma<<<dim3(MTOK / 128, QW / 128), 256, GEMM_SMEM>>>(
        MTOK, QW, H_, xh, Wqh, qkvz, (fp16*)0);
    conv_silu_kernel<<<(MTOK * CDIM / 4) / 256, 256>>>(qkvz, cw, cb, conv);
    norm_qk_kernel<<<MTOK * HK_, 128>>>(conv, qn, kn);
    gates_kernel<<<MTOK, 32>>>(qkvz, A_log, dtb, gg, bb);
    scan_kernel<<<B_ * HV_ * 2, 256>>>(qn, kn, conv, gg, bb, o);
    gated_norm_split<<<MTOK * HV_, 128>>>(o, qkvz, nw, oh);
    gemm_mma<<<dim3(MTOK / 128, H_ / 128), 256, GEMM_SMEM>>>(
        MTOK, H_, VDIM, oh, Woh, (float*)0, hh);
    gemm_mma<<<dim3(MTOK / 128, V_ / 128), 256, GEMM_SMEM>>>(
        MTOK, V_, H_, hh, Wlh, out, (fp16*)0);
}